// round 4
// baseline (speedup 1.0000x reference)
#include <cuda_runtime.h>
#include <cstdint>
#include <cstddef>

#define NNODES 50000
#define NEDGES 1600000
#define HDIM   64
#define FNODE  8
#define FEDGE  8
#define NCLS   10

// ---------------- scratch (device globals; no allocation allowed) ----------
__device__ __align__(16) float g_h   [NNODES * HDIM];   // current node features
__device__ __align__(16) float g_g   [NNODES * HDIM];   // (h@W)*dinv  (gather source)
__device__ __align__(16) float g_acc [NNODES * HDIM];   // scatter accumulator
__device__ __align__(16) float g_dinv[NNODES];          // 1/sqrt(deg)
__device__ __align__(16) float g_P   [NNODES * HDIM];   // h@W1a + b1
__device__ __align__(16) float g_Q   [NNODES * HDIM];   // h@W1b

// ---------------- node encoder: h = x @ W_node + b_node --------------------
__global__ void __launch_bounds__(256) encoder_kernel(
    const float* __restrict__ x, const float* __restrict__ Wn,
    const float* __restrict__ bn)
{
    __shared__ float Ws[FNODE * HDIM];
    int tid = threadIdx.x;
    for (int i = tid; i < FNODE * HDIM; i += 256) Ws[i] = Wn[i];
    __syncthreads();
    int t = blockIdx.x * 256 + tid;          // t < N*64 (exact)
    int n = t >> 6, j = t & 63;
    float s = bn[j];
#pragma unroll
    for (int k = 0; k < FNODE; k++)
        s = fmaf(x[n * FNODE + k], Ws[k * HDIM + j], s);
    g_h[t] = s;
}

// ---------------- degree / dinv -------------------------------------------
__global__ void deg_init_kernel() {
    int n = blockIdx.x * 256 + threadIdx.x;
    if (n < NNODES) g_dinv[n] = 1.0f;        // self-loop
}
__global__ void deg_count_kernel(const int* __restrict__ dst) {
    int e = blockIdx.x * 256 + threadIdx.x;
    if (e < NEDGES) atomicAdd(&g_dinv[dst[e]], 1.0f);
}
__global__ void deg_finish_kernel() {
    int n = blockIdx.x * 256 + threadIdx.x;
    if (n < NNODES) g_dinv[n] = rsqrtf(g_dinv[n]);
}

// ------------- GCN transform: g = (h @ W) * dinv; acc = g (self-loop) ------
__global__ void __launch_bounds__(256) gcn_transform_kernel(
    const float* __restrict__ W)
{
    __shared__ float Ws[HDIM * HDIM];
    __shared__ float hs[4 * HDIM];
    int tid = threadIdx.x;
#pragma unroll 4
    for (int i = tid; i < HDIM * HDIM; i += 256) Ws[i] = W[i];
    int n0 = blockIdx.x * 4;
    hs[tid] = g_h[n0 * HDIM + tid];          // 4 contiguous rows
    __syncthreads();
    int nn = tid >> 6, j = tid & 63;
    float s = 0.f;
#pragma unroll
    for (int k = 0; k < HDIM; k++)
        s = fmaf(hs[nn * HDIM + k], Ws[k * HDIM + j], s);
    int n = n0 + nn;
    float gg = s * g_dinv[n];
    g_g[n * HDIM + j]   = gg;
    g_acc[n * HDIM + j] = gg;                // self-loop term: dinv[n]*g[n] later
}

// ------------- edge scatter: acc[dst] += g[src]  (vector f32x4 RED) --------
__global__ void __launch_bounds__(256) scatter_kernel(
    const int* __restrict__ src, const int* __restrict__ dst)
{
    long long t = (long long)blockIdx.x * 256 + threadIdx.x;  // E*16 threads
    int e = (int)(t >> 4);
    int q = ((int)t & 15) * 4;
    int s = src[e], d = dst[e];
    const float4 v = *(const float4*)(g_g + (size_t)s * HDIM + q);
    float* p = g_acc + (size_t)d * HDIM + q;
    asm volatile("red.global.add.v4.f32 [%0], {%1,%2,%3,%4};"
                 :: "l"(p), "f"(v.x), "f"(v.y), "f"(v.z), "f"(v.w)
                 : "memory");
}

// ------------- GCN finish: h = relu(dinv[n]*acc + b) -----------------------
__global__ void __launch_bounds__(256) gcn_finish_kernel(
    const float* __restrict__ b)
{
    int t = blockIdx.x * 256 + threadIdx.x;  // N*64 exact
    int n = t >> 6, j = t & 63;
    g_h[t] = fmaxf(fmaf(g_dinv[n], g_acc[t], b[j]), 0.f);
}

// ------------- P = h@W1a + b1 ; Q = h@W1b  (node-level precompute) ---------
__global__ void __launch_bounds__(256) pq_kernel(
    const float* __restrict__ W1, const float* __restrict__ b1)
{
    __shared__ float Ws[2 * HDIM * HDIM];    // W1 rows 0..127 (32 KB)
    __shared__ float hs[4 * HDIM];
    int tid = threadIdx.x;
#pragma unroll 8
    for (int i = tid; i < 2 * HDIM * HDIM; i += 256) Ws[i] = W1[i];
    int n0 = blockIdx.x * 4;
    hs[tid] = g_h[n0 * HDIM + tid];
    __syncthreads();
    int nn = tid >> 6, j = tid & 63;
    float p = b1[j], q = 0.f;
#pragma unroll
    for (int k = 0; k < HDIM; k++) {
        float hv = hs[nn * HDIM + k];
        p = fmaf(hv, Ws[k * HDIM + j], p);
        q = fmaf(hv, Ws[(HDIM + k) * HDIM + j], q);
    }
    int n = n0 + nn;
    g_P[n * HDIM + j] = p;
    g_Q[n * HDIM + j] = q;
}

// ------------- edge MLP: z1=relu(P[s]+Q[d]+attr@W1c); z2=relu(z1@W2+b2);
//               out = z2@W3 + b3.  One warp per edge, 16 edges per warp. ----
__global__ void __launch_bounds__(256) edge_mlp_kernel(
    const int*   __restrict__ src, const int* __restrict__ dst,
    const float* __restrict__ ea,
    const float* __restrict__ W1,
    const float* __restrict__ W2,  const float* __restrict__ b2,
    const float* __restrict__ W3,  const float* __restrict__ b3,
    float*       __restrict__ out)
{
    __shared__ float W1cs[FEDGE * HDIM];     // rows 128..135 of W1
    __shared__ float W2s[HDIM * 32];
    __shared__ float W3s[32 * NCLS];
    __shared__ float b2s[32];
    __shared__ float b3s[16];
    int tid = threadIdx.x;
    for (int i = tid; i < FEDGE * HDIM; i += 256) W1cs[i] = W1[2 * HDIM * HDIM + i];
    for (int i = tid; i < HDIM * 32;   i += 256) W2s[i]  = W2[i];
    for (int i = tid; i < 32 * NCLS;   i += 256) W3s[i]  = W3[i];
    if (tid < 32)        b2s[tid] = b2[tid];
    if (tid < 16)        b3s[tid] = (tid < NCLS) ? b3[tid] : 0.f;
    __syncthreads();

    int warp = tid >> 5, lane = tid & 31;
    int ebase = blockIdx.x * 128 + warp * 16;

#pragma unroll 1
    for (int it = 0; it < 16; ++it) {
        int e = ebase + it;                  // E = 12500*128 exact, no guard
        int s = src[e], d = dst[e];
        size_t so = (size_t)s * HDIM, dof = (size_t)d * HDIM;

        float z1a = g_P[so + lane]      + g_Q[dof + lane];
        float z1b = g_P[so + 32 + lane] + g_Q[dof + 32 + lane];

        float a = (lane < FEDGE) ? ea[(size_t)e * FEDGE + lane] : 0.f;
#pragma unroll
        for (int k = 0; k < FEDGE; k++) {
            float ak = __shfl_sync(0xffffffffu, a, k);
            z1a = fmaf(ak, W1cs[k * HDIM + lane],      z1a);
            z1b = fmaf(ak, W1cs[k * HDIM + 32 + lane], z1b);
        }
        z1a = fmaxf(z1a, 0.f);
        z1b = fmaxf(z1b, 0.f);

        float z2 = b2s[lane];
#pragma unroll
        for (int k = 0; k < 32; k++)
            z2 = fmaf(__shfl_sync(0xffffffffu, z1a, k), W2s[k * 32 + lane], z2);
#pragma unroll
        for (int k = 0; k < 32; k++)
            z2 = fmaf(__shfl_sync(0xffffffffu, z1b, k), W2s[(k + 32) * 32 + lane], z2);
        z2 = fmaxf(z2, 0.f);

        float o = (lane < 16) ? b3s[lane] : 0.f;
#pragma unroll
        for (int k = 0; k < 32; k++) {
            float v = __shfl_sync(0xffffffffu, z2, k);
            if (lane < NCLS) o = fmaf(v, W3s[k * NCLS + lane], o);
        }
        if (lane < NCLS) out[(size_t)e * NCLS + lane] = o;
    }
}

// ---------------------------------------------------------------------------
extern "C" void kernel_launch(void* const* d_in, const int* in_sizes, int n_in,
                              void* d_out, int out_size)
{
    const float* x  = (const float*)d_in[0];
    const int*   ei = (const int*)  d_in[1];
    const float* ea = (const float*)d_in[2];
    const float* Wn = (const float*)d_in[3];
    const float* bn = (const float*)d_in[4];
    const float* Wc = (const float*)d_in[5];   // [3,64,64]
    const float* bc = (const float*)d_in[6];   // [3,64]
    const float* W1 = (const float*)d_in[7];   // [136,64]
    const float* b1 = (const float*)d_in[8];
    const float* W2 = (const float*)d_in[9];   // [64,32]
    const float* b2 = (const float*)d_in[10];
    const float* W3 = (const float*)d_in[11];  // [32,10]
    const float* b3 = (const float*)d_in[12];
    const int* src = ei;
    const int* dst = ei + NEDGES;
    float* out = (float*)d_out;

    const int NH_BLKS = (NNODES * HDIM) / 256;       // 12500 exact
    const int N_BLKS  = (NNODES + 255) / 256;        // 196
    const int E_BLKS  = NEDGES / 256;                // 6250 exact

    // encoder
    encoder_kernel<<<NH_BLKS, 256>>>(x, Wn, bn);

    // degrees
    deg_init_kernel<<<N_BLKS, 256>>>();
    deg_count_kernel<<<E_BLKS, 256>>>(dst);
    deg_finish_kernel<<<N_BLKS, 256>>>();

    // 3 GCN layers
    for (int l = 0; l < 3; l++) {
        gcn_transform_kernel<<<NNODES / 4, 256>>>(Wc + l * HDIM * HDIM);
        scatter_kernel<<<(NEDGES * 16) / 256, 256>>>(src, dst);
        gcn_finish_kernel<<<NH_BLKS, 256>>>(bc + l * HDIM);
    }

    // node-level halves of the first edge-MLP layer
    pq_kernel<<<NNODES / 4, 256>>>(W1, b1);

    // per-edge MLP (warp per edge, 16 edges per warp)
    edge_mlp_kernel<<<NEDGES / 128, 256>>>(src, dst, ea, W1, W2, b2, W3, b3, out);
}

// round 6
// speedup vs baseline: 1.5991x; 1.5991x over previous
#include <cuda_runtime.h>
#include <cstdint>
#include <cstddef>

#define NNODES 50000
#define NEDGES 1600000
#define HDIM   64
#define FNODE  8
#define FEDGE  8
#define NCLS   10

// ---------------- scratch (device globals; no allocation allowed) ----------
__device__ __align__(16) float g_h   [NNODES * HDIM];
__device__ __align__(16) float g_g   [NNODES * HDIM];
__device__ __align__(16) float g_acc [NNODES * HDIM];
__device__ __align__(16) float g_dinv[NNODES];
__device__ __align__(16) float g_P   [NNODES * HDIM];   // h@W1a + b1
__device__ __align__(16) float g_Q   [NNODES * HDIM];   // h@W1b

// ---------------- node encoder: h = x @ W_node + b_node --------------------
__global__ void __launch_bounds__(256) encoder_kernel(
    const float* __restrict__ x, const float* __restrict__ Wn,
    const float* __restrict__ bn)
{
    __shared__ float Ws[FNODE * HDIM];
    int tid = threadIdx.x;
    for (int i = tid; i < FNODE * HDIM; i += 256) Ws[i] = Wn[i];
    __syncthreads();
    int t = blockIdx.x * 256 + tid;
    int n = t >> 6, j = t & 63;
    float s = bn[j];
#pragma unroll
    for (int k = 0; k < FNODE; k++)
        s = fmaf(x[n * FNODE + k], Ws[k * HDIM + j], s);
    g_h[t] = s;
}

// ---------------- degree / dinv -------------------------------------------
__global__ void deg_init_kernel() {
    int n = blockIdx.x * 256 + threadIdx.x;
    if (n < NNODES) g_dinv[n] = 1.0f;
}
__global__ void deg_count_kernel(const int* __restrict__ dst) {
    int e = blockIdx.x * 256 + threadIdx.x;
    if (e < NEDGES) atomicAdd(&g_dinv[dst[e]], 1.0f);
}
__global__ void deg_finish_kernel() {
    int n = blockIdx.x * 256 + threadIdx.x;
    if (n < NNODES) g_dinv[n] = rsqrtf(g_dinv[n]);
}

// ------------- GCN transform: g = (h @ W) * dinv; acc = g (self-loop) ------
__global__ void __launch_bounds__(256) gcn_transform_kernel(
    const float* __restrict__ W)
{
    __shared__ float Ws[HDIM * HDIM];
    __shared__ float hs[4 * HDIM];
    int tid = threadIdx.x;
#pragma unroll 4
    for (int i = tid; i < HDIM * HDIM; i += 256) Ws[i] = W[i];
    int n0 = blockIdx.x * 4;
    hs[tid] = g_h[n0 * HDIM + tid];
    __syncthreads();
    int nn = tid >> 6, j = tid & 63;
    float s = 0.f;
#pragma unroll
    for (int k = 0; k < HDIM; k++)
        s = fmaf(hs[nn * HDIM + k], Ws[k * HDIM + j], s);
    int n = n0 + nn;
    float gg = s * g_dinv[n];
    g_g[n * HDIM + j]   = gg;
    g_acc[n * HDIM + j] = gg;
}

// ------------- edge scatter: acc[dst] += g[src]  (vector f32x4 RED) --------
__global__ void __launch_bounds__(256) scatter_kernel(
    const int* __restrict__ src, const int* __restrict__ dst)
{
    long long t = (long long)blockIdx.x * 256 + threadIdx.x;
    int e = (int)(t >> 4);
    int q = ((int)t & 15) * 4;
    int s = src[e], d = dst[e];
    const float4 v = *(const float4*)(g_g + (size_t)s * HDIM + q);
    float* p = g_acc + (size_t)d * HDIM + q;
    asm volatile("red.global.add.v4.f32 [%0], {%1,%2,%3,%4};"
                 :: "l"(p), "f"(v.x), "f"(v.y), "f"(v.z), "f"(v.w)
                 : "memory");
}

// ------------- GCN finish: h = relu(dinv[n]*acc + b) -----------------------
__global__ void __launch_bounds__(256) gcn_finish_kernel(
    const float* __restrict__ b)
{
    int t = blockIdx.x * 256 + threadIdx.x;
    int n = t >> 6, j = t & 63;
    g_h[t] = fmaxf(fmaf(g_dinv[n], g_acc[t], b[j]), 0.f);
}

// ------------- P = h@W1a + b1 ; Q = h@W1b  (node-level precompute) ---------
__global__ void __launch_bounds__(256) pq_kernel(
    const float* __restrict__ W1, const float* __restrict__ b1)
{
    __shared__ float Ws[2 * HDIM * HDIM];
    __shared__ float hs[4 * HDIM];
    int tid = threadIdx.x;
#pragma unroll 8
    for (int i = tid; i < 2 * HDIM * HDIM; i += 256) Ws[i] = W1[i];
    int n0 = blockIdx.x * 4;
    hs[tid] = g_h[n0 * HDIM + tid];
    __syncthreads();
    int nn = tid >> 6, j = tid & 63;
    float p = b1[j], q = 0.f;
#pragma unroll
    for (int k = 0; k < HDIM; k++) {
        float hv = hs[nn * HDIM + k];
        p = fmaf(hv, Ws[k * HDIM + j], p);
        q = fmaf(hv, Ws[(HDIM + k) * HDIM + j], q);
    }
    int n = n0 + nn;
    g_P[n * HDIM + j] = p;
    g_Q[n * HDIM + j] = q;
}

// ======================= edge MLP v2: tiled, shuffle-free ===================
#define TILE_E 64
#define NTILE  8
#define SP1    68   // z1p row stride (floats)
#define SP2    36   // z2s row stride (floats)

__global__ void __launch_bounds__(128) edge_mlp_v2_kernel(
    const int*   __restrict__ src, const int* __restrict__ dst,
    const float* __restrict__ ea,
    const float* __restrict__ W1,
    const float* __restrict__ W2,  const float* __restrict__ b2,
    const float* __restrict__ W3,  const float* __restrict__ b3,
    float*       __restrict__ out)
{
    __shared__ float  z1p[HDIM * SP1];
    __shared__ float  z2s[TILE_E * SP2];
    __shared__ float2 W2d[HDIM * 32];
    __shared__ float  W1cs[FEDGE * HDIM];
    __shared__ float  W3ts[NCLS * 32];
    __shared__ float  b2s[32];
    __shared__ float  b3s[NCLS];

    int tid = threadIdx.x;

    for (int i = tid; i < FEDGE * HDIM; i += 128) W1cs[i] = W1[2 * HDIM * HDIM + i];
    for (int i = tid; i < HDIM * 32; i += 128) {
        float w = W2[i];
        W2d[i] = make_float2(w, w);
    }
    for (int i = tid; i < NCLS * 32; i += 128) {
        int j = i >> 5, k = i & 31;
        W3ts[i] = W3[k * NCLS + j];
    }
    if (tid < 32)  b2s[tid] = b2[tid];
    if (tid < NCLS) b3s[tid] = b3[tid];
    __syncthreads();

    uint32_t z1b = (uint32_t)__cvta_generic_to_shared(z1p);
    uint32_t w2b = (uint32_t)__cvta_generic_to_shared(W2d);

    int el = tid >> 1;
    int hf = tid & 1;
    int eg = tid & 15;
    int cg = tid >> 4;
    int j0 = cg * 4;

#pragma unroll 1
    for (int it = 0; it < NTILE; ++it) {
        int ebase = (blockIdx.x * NTILE + it) * TILE_E;

        // ---------------- Phase 1 ----------------
        {
            int e = ebase + el;
            int s = src[e], d = dst[e];
            const float4* Pp = (const float4*)(g_P + (size_t)s * HDIM + hf * 32);
            const float4* Qp = (const float4*)(g_Q + (size_t)d * HDIM + hf * 32);
            float4 acc[8];
#pragma unroll
            for (int q = 0; q < 8; q++) {
                float4 pv = Pp[q], qv = Qp[q];
                acc[q].x = pv.x + qv.x; acc[q].y = pv.y + qv.y;
                acc[q].z = pv.z + qv.z; acc[q].w = pv.w + qv.w;
            }
            const float4* eap = (const float4*)(ea + (size_t)e * FEDGE);
            float4 a0 = eap[0], a1 = eap[1];
            float av[8] = {a0.x, a0.y, a0.z, a0.w, a1.x, a1.y, a1.z, a1.w};
            const float4* W1c4 = (const float4*)W1cs;
#pragma unroll
            for (int k = 0; k < FEDGE; k++) {
                float ak = av[k];
#pragma unroll
                for (int q = 0; q < 8; q++) {
                    float4 w = W1c4[k * 16 + hf * 8 + q];
                    acc[q].x = fmaf(ak, w.x, acc[q].x);
                    acc[q].y = fmaf(ak, w.y, acc[q].y);
                    acc[q].z = fmaf(ak, w.z, acc[q].z);
                    acc[q].w = fmaf(ak, w.w, acc[q].w);
                }
            }
#pragma unroll
            for (int q = 0; q < 8; q++) {
                int k = hf * 32 + q * 4;
                z1p[(k + 0) * SP1 + el] = fmaxf(acc[q].x, 0.f);
                z1p[(k + 1) * SP1 + el] = fmaxf(acc[q].y, 0.f);
                z1p[(k + 2) * SP1 + el] = fmaxf(acc[q].z, 0.f);
                z1p[(k + 3) * SP1 + el] = fmaxf(acc[q].w, 0.f);
            }
        }
        __syncthreads();

        // ---------------- Phase 2 ----------------
        {
            uint64_t acc01[4], acc23[4];
#pragma unroll
            for (int j = 0; j < 4; j++) {
                float bv = b2s[j0 + j];
                uint64_t bb;
                asm("mov.b64 %0, {%1, %1};" : "=l"(bb) : "f"(bv));
                acc01[j] = bb; acc23[j] = bb;
            }
            uint32_t za = z1b + eg * 16;
            uint32_t wa = w2b + j0 * 8;
#pragma unroll 16
            for (int k = 0; k < HDIM; k++) {
                uint64_t z01, z23, w0, w1, w2v, w3v;
                asm("ld.shared.v2.b64 {%0,%1}, [%2];"
                    : "=l"(z01), "=l"(z23) : "r"(za + k * (SP1 * 4)));
                asm("ld.shared.v2.b64 {%0,%1}, [%2];"
                    : "=l"(w0), "=l"(w1) : "r"(wa + k * 256));
                asm("ld.shared.v2.b64 {%0,%1}, [%2];"
                    : "=l"(w2v), "=l"(w3v) : "r"(wa + k * 256 + 16));
                asm("fma.rn.f32x2 %0, %1, %2, %0;" : "+l"(acc01[0]) : "l"(z01), "l"(w0));
                asm("fma.rn.f32x2 %0, %1, %2, %0;" : "+l"(acc23[0]) : "l"(z23), "l"(w0));
                asm("fma.rn.f32x2 %0, %1, %2, %0;" : "+l"(acc01[1]) : "l"(z01), "l"(w1));
                asm("fma.rn.f32x2 %0, %1, %2, %0;" : "+l"(acc23[1]) : "l"(z23), "l"(w1));
                asm("fma.rn.f32x2 %0, %1, %2, %0;" : "+l"(acc01[2]) : "l"(z01), "l"(w2v));
                asm("fma.rn.f32x2 %0, %1, %2, %0;" : "+l"(acc23[2]) : "l"(z23), "l"(w2v));
                asm("fma.rn.f32x2 %0, %1, %2, %0;" : "+l"(acc01[3]) : "l"(z01), "l"(w3v));
                asm("fma.rn.f32x2 %0, %1, %2, %0;" : "+l"(acc23[3]) : "l"(z23), "l"(w3v));
            }
            float v0[4], v1[4], v2[4], v3[4];
#pragma unroll
            for (int j = 0; j < 4; j++) {
                float lo, hi;
                asm("mov.b64 {%0,%1}, %2;" : "=f"(lo), "=f"(hi) : "l"(acc01[j]));
                v0[j] = fmaxf(lo, 0.f); v1[j] = fmaxf(hi, 0.f);
                asm("mov.b64 {%0,%1}, %2;" : "=f"(lo), "=f"(hi) : "l"(acc23[j]));
                v2[j] = fmaxf(lo, 0.f); v3[j] = fmaxf(hi, 0.f);
            }
            int e0 = eg * 4;
            *(float4*)&z2s[(e0 + 0) * SP2 + j0] = make_float4(v0[0], v0[1], v0[2], v0[3]);
            *(float4*)&z2s[(e0 + 1) * SP2 + j0] = make_float4(v1[0], v1[1], v1[2], v1[3]);
            *(float4*)&z2s[(e0 + 2) * SP2 + j0] = make_float4(v2[0], v2[1], v2[2], v2[3]);
            *(float4*)&z2s[(e0 + 3) * SP2 + j0] = make_float4(v3[0], v3[1], v3[2], v3[3]);
        }
        __syncthreads();

        // ---------------- Phase 3 ----------------
        {
            int jo = hf * 5;
            float acc[5];
#pragma unroll
            for (int j = 0; j < 5; j++) acc[j] = b3s[jo + j];
            const float4* z2v = (const float4*)&z2s[el * SP2];
#pragma unroll
            for (int k4 = 0; k4 < 8; k4++) {
                float4 z = z2v[k4];
#pragma unroll
                for (int j = 0; j < 5; j++) {
                    float4 w = *(const float4*)&W3ts[(jo + j) * 32 + k4 * 4];
                    acc[j] = fmaf(z.x, w.x, acc[j]);
                    acc[j] = fmaf(z.y, w.y, acc[j]);
                    acc[j] = fmaf(z.z, w.z, acc[j]);
                    acc[j] = fmaf(z.w, w.w, acc[j]);
                }
            }
            float* op = out + (size_t)(ebase + el) * NCLS + jo;
#pragma unroll
            for (int j = 0; j < 5; j++) op[j] = acc[j];
        }
        __syncthreads();
    }
}

// ---------------------------------------------------------------------------
extern "C" void kernel_launch(void* const* d_in, const int* in_sizes, int n_in,
                              void* d_out, int out_size)
{
    const float* x  = (const float*)d_in[0];
    const int*   ei = (const int*)  d_in[1];
    const float* ea = (const float*)d_in[2];
    const float* Wn = (const float*)d_in[3];
    const float* bn = (const float*)d_in[4];
    const float* Wc = (const float*)d_in[5];
    const float* bc = (const float*)d_in[6];
    const float* W1 = (const float*)d_in[7];
    const float* b1 = (const float*)d_in[8];
    const float* W2 = (const float*)d_in[9];
    const float* b2 = (const float*)d_in[10];
    const float* W3 = (const float*)d_in[11];
    const float* b3 = (const float*)d_in[12];
    const int* src = ei;
    const int* dst = ei + NEDGES;
    float* out = (float*)d_out;

    const int NH_BLKS = (NNODES * HDIM) / 256;
    const int N_BLKS  = (NNODES + 255) / 256;
    const int E_BLKS  = NEDGES / 256;

    encoder_kernel<<<NH_BLKS, 256>>>(x, Wn, bn);

    deg_init_kernel<<<N_BLKS, 256>>>();
    deg_count_kernel<<<E_BLKS, 256>>>(dst);
    deg_finish_kernel<<<N_BLKS, 256>>>();

    for (int l = 0; l < 3; l++) {
        gcn_transform_kernel<<<NNODES / 4, 256>>>(Wc + l * HDIM * HDIM);
        scatter_kernel<<<(NEDGES * 16) / 256, 256>>>(src, dst);
        gcn_finish_kernel<<<NH_BLKS, 256>>>(bc + l * HDIM);
    }

    pq_kernel<<<NNODES / 4, 256>>>(W1, b1);

    edge_mlp_v2_kernel<<<NEDGES / (TILE_E * NTILE), 128>>>(
        src, dst, ea, W1, W2, b2, W3, b3, out);
}

// round 9
// speedup vs baseline: 1.7903x; 1.1196x over previous
#include <cuda_runtime.h>
#include <cstdint>
#include <cstddef>

#define NNODES 50000
#define NEDGES 1600000
#define HDIM   64
#define FNODE  8
#define FEDGE  8
#define NCLS   10

// ---------------- scratch (device globals; no allocation allowed) ----------
__device__ __align__(16) float g_h   [NNODES * HDIM];
__device__ __align__(16) float g_g   [NNODES * HDIM];
__device__ __align__(16) float g_dinv[NNODES];
__device__ __align__(16) float g_P   [NNODES * HDIM];
__device__ __align__(16) float g_Q   [NNODES * HDIM];
__device__ int  g_deg[NNODES];
__device__ int  g_off[NNODES + 1];
__device__ int  g_cur[NNODES];
__device__ int  g_csr[NEDGES];          // src indices grouped by dst

// ---------------- node encoder: h = x @ W_node + b_node --------------------
__global__ void __launch_bounds__(256) encoder_kernel(
    const float* __restrict__ x, const float* __restrict__ Wn,
    const float* __restrict__ bn)
{
    __shared__ float Ws[FNODE * HDIM];
    int tid = threadIdx.x;
    for (int i = tid; i < FNODE * HDIM; i += 256) Ws[i] = Wn[i];
    __syncthreads();
    int t = blockIdx.x * 256 + tid;
    int n = t >> 6, j = t & 63;
    float s = bn[j];
#pragma unroll
    for (int k = 0; k < FNODE; k++)
        s = fmaf(x[n * FNODE + k], Ws[k * HDIM + j], s);
    g_h[t] = s;
}

// ---------------- CSR build ------------------------------------------------
__global__ void zero_deg_kernel() {
    int n = blockIdx.x * 256 + threadIdx.x;
    if (n < NNODES) g_deg[n] = 0;
}
__global__ void hist_kernel(const int* __restrict__ dst) {
    int e = blockIdx.x * 256 + threadIdx.x;
    if (e < NEDGES) atomicAdd(&g_deg[dst[e]], 1);
}
// single-block exclusive scan over g_deg -> g_off/g_cur; also dinv = rsqrt(deg+1)
__global__ void __launch_bounds__(1024) scan_kernel() {
    __shared__ int carry;
    __shared__ int warp_tot[32];
    int tid = threadIdx.x, lane = tid & 31, wid = tid >> 5;
    if (tid == 0) carry = 0;
    __syncthreads();
    for (int base = 0; base < NNODES; base += 1024) {
        int n = base + tid;
        int v = (n < NNODES) ? g_deg[n] : 0;
        int x = v;
#pragma unroll
        for (int o = 1; o < 32; o <<= 1) {
            int y = __shfl_up_sync(0xffffffffu, x, o);
            if (lane >= o) x += y;
        }
        if (lane == 31) warp_tot[wid] = x;
        __syncthreads();
        if (wid == 0) {
            int t = warp_tot[lane];
#pragma unroll
            for (int o = 1; o < 32; o <<= 1) {
                int y = __shfl_up_sync(0xffffffffu, t, o);
                if (lane >= o) t += y;
            }
            warp_tot[lane] = t;
        }
        __syncthreads();
        int incl = x + (wid > 0 ? warp_tot[wid - 1] : 0) + carry;
        if (n < NNODES) {
            int excl = incl - v;
            g_off[n] = excl;
            g_cur[n] = excl;
            g_dinv[n] = rsqrtf((float)(v + 1));   // +1 self-loop
        }
        __syncthreads();
        if (tid == 1023) carry = incl;
        __syncthreads();
    }
    if (tid == 0) g_off[NNODES] = NEDGES;
}
__global__ void fill_kernel(const int* __restrict__ src, const int* __restrict__ dst) {
    int e = blockIdx.x * 256 + threadIdx.x;
    if (e < NEDGES) {
        int pos = atomicAdd(&g_cur[dst[e]], 1);
        g_csr[pos] = src[e];
    }
}

// ------------- GCN transform: g = (h @ W) * dinv ---------------------------
__global__ void __launch_bounds__(256) gcn_transform_kernel(
    const float* __restrict__ W)
{
    __shared__ float Ws[HDIM * HDIM];
    __shared__ float hs[4 * HDIM];
    int tid = threadIdx.x;
#pragma unroll 4
    for (int i = tid; i < HDIM * HDIM; i += 256) Ws[i] = W[i];
    int n0 = blockIdx.x * 4;
    hs[tid] = g_h[n0 * HDIM + tid];
    __syncthreads();
    int nn = tid >> 6, j = tid & 63;
    float s = 0.f;
#pragma unroll
    for (int k = 0; k < HDIM; k++)
        s = fmaf(hs[nn * HDIM + k], Ws[k * HDIM + j], s);
    int n = n0 + nn;
    g_g[n * HDIM + j] = s * g_dinv[n];
}

// ------------- GCN gather+finish: warp per node, no atomics ----------------
__global__ void __launch_bounds__(256) gcn_gather_kernel(
    const float* __restrict__ b)
{
    int n = (blockIdx.x * 256 + threadIdx.x) >> 5;
    if (n >= NNODES) return;
    int lane = threadIdx.x & 31;
    int beg = g_off[n], end = g_off[n + 1];
    float a0 = g_g[(size_t)n * HDIM + lane];
    float a1 = g_g[(size_t)n * HDIM + 32 + lane];
    int j = beg;
    for (; j + 4 <= end; j += 4) {
        int s0 = g_csr[j], s1 = g_csr[j + 1], s2 = g_csr[j + 2], s3 = g_csr[j + 3];
        float v00 = g_g[(size_t)s0 * HDIM + lane];
        float v01 = g_g[(size_t)s0 * HDIM + 32 + lane];
        float v10 = g_g[(size_t)s1 * HDIM + lane];
        float v11 = g_g[(size_t)s1 * HDIM + 32 + lane];
        float v20 = g_g[(size_t)s2 * HDIM + lane];
        float v21 = g_g[(size_t)s2 * HDIM + 32 + lane];
        float v30 = g_g[(size_t)s3 * HDIM + lane];
        float v31 = g_g[(size_t)s3 * HDIM + 32 + lane];
        a0 += v00 + v10 + v20 + v30;
        a1 += v01 + v11 + v21 + v31;
    }
    for (; j < end; j++) {
        int s = g_csr[j];
        a0 += g_g[(size_t)s * HDIM + lane];
        a1 += g_g[(size_t)s * HDIM + 32 + lane];
    }
    float di = g_dinv[n];
    g_h[(size_t)n * HDIM + lane]      = fmaxf(fmaf(di, a0, b[lane]),      0.f);
    g_h[(size_t)n * HDIM + 32 + lane] = fmaxf(fmaf(di, a1, b[lane + 32]), 0.f);
}

// ------------- P = h@W1a + b1 ; Q = h@W1b ----------------------------------
__global__ void __launch_bounds__(256) pq_kernel(
    const float* __restrict__ W1, const float* __restrict__ b1)
{
    __shared__ float Ws[2 * HDIM * HDIM];
    __shared__ float hs[4 * HDIM];
    int tid = threadIdx.x;
#pragma unroll 8
    for (int i = tid; i < 2 * HDIM * HDIM; i += 256) Ws[i] = W1[i];
    int n0 = blockIdx.x * 4;
    hs[tid] = g_h[n0 * HDIM + tid];
    __syncthreads();
    int nn = tid >> 6, j = tid & 63;
    float p = b1[j], q = 0.f;
#pragma unroll
    for (int k = 0; k < HDIM; k++) {
        float hv = hs[nn * HDIM + k];
        p = fmaf(hv, Ws[k * HDIM + j], p);
        q = fmaf(hv, Ws[(HDIM + k) * HDIM + j], q);
    }
    int n = n0 + nn;
    g_P[n * HDIM + j] = p;
    g_Q[n * HDIM + j] = q;
}

// ======================= edge MLP v2 ====================
#define TILE_E 64
#define NTILE  8
#define SP1    68
#define SP2    36

__global__ void __launch_bounds__(128) edge_mlp_v2_kernel(
    const int*   __restrict__ src, const int* __restrict__ dst,
    const float* __restrict__ ea,
    const float* __restrict__ W1,
    const float* __restrict__ W2,  const float* __restrict__ b2,
    const float* __restrict__ W3,  const float* __restrict__ b3,
    float*       __restrict__ out)
{
    __shared__ float  z1p[HDIM * SP1];
    __shared__ float  z2s[TILE_E * SP2];
    __shared__ float2 W2d[HDIM * 32];
    __shared__ float  W1cs[FEDGE * HDIM];
    __shared__ float  W3ts[NCLS * 32];
    __shared__ float  b2s[32];
    __shared__ float  b3s[NCLS];

    int tid = threadIdx.x;

    for (int i = tid; i < FEDGE * HDIM; i += 128) W1cs[i] = W1[2 * HDIM * HDIM + i];
    for (int i = tid; i < HDIM * 32; i += 128) {
        float w = W2[i];
        W2d[i] = make_float2(w, w);
    }
    for (int i = tid; i < NCLS * 32; i += 128) {
        int j = i >> 5, k = i & 31;
        W3ts[i] = W3[k * NCLS + j];
    }
    if (tid < 32)  b2s[tid] = b2[tid];
    if (tid < NCLS) b3s[tid] = b3[tid];
    __syncthreads();

    uint32_t z1b = (uint32_t)__cvta_generic_to_shared(z1p);
    uint32_t w2b = (uint32_t)__cvta_generic_to_shared(W2d);

    int el = tid >> 1;
    int hf = tid & 1;
    int eg = tid & 15;
    int cg = tid >> 4;
    int j0 = cg * 4;

#pragma unroll 1
    for (int it = 0; it < NTILE; ++it) {
        int ebase = (blockIdx.x * NTILE + it) * TILE_E;

        // ---------------- Phase 1 ----------------
        {
            int e = ebase + el;
            int s = src[e], d = dst[e];
            const float4* Pp = (const float4*)(g_P + (size_t)s * HDIM + hf * 32);
            const float4* Qp = (const float4*)(g_Q + (size_t)d * HDIM + hf * 32);
            float4 acc[8];
#pragma unroll
            for (int q = 0; q < 8; q++) {
                float4 pv = Pp[q], qv = Qp[q];
                acc[q].x = pv.x + qv.x; acc[q].y = pv.y + qv.y;
                acc[q].z = pv.z + qv.z; acc[q].w = pv.w + qv.w;
            }
            const float4* eap = (const float4*)(ea + (size_t)e * FEDGE);
            float4 a0 = eap[0], a1 = eap[1];
            float av[8] = {a0.x, a0.y, a0.z, a0.w, a1.x, a1.y, a1.z, a1.w};
            const float4* W1c4 = (const float4*)W1cs;
#pragma unroll
            for (int k = 0; k < FEDGE; k++) {
                float ak = av[k];
#pragma unroll
                for (int q = 0; q < 8; q++) {
                    float4 w = W1c4[k * 16 + hf * 8 + q];
                    acc[q].x = fmaf(ak, w.x, acc[q].x);
                    acc[q].y = fmaf(ak, w.y, acc[q].y);
                    acc[q].z = fmaf(ak, w.z, acc[q].z);
                    acc[q].w = fmaf(ak, w.w, acc[q].w);
                }
            }
#pragma unroll
            for (int q = 0; q < 8; q++) {
                int k = hf * 32 + q * 4;
                z1p[(k + 0) * SP1 + el] = fmaxf(acc[q].x, 0.f);
                z1p[(k + 1) * SP1 + el] = fmaxf(acc[q].y, 0.f);
                z1p[(k + 2) * SP1 + el] = fmaxf(acc[q].z, 0.f);
                z1p[(k + 3) * SP1 + el] = fmaxf(acc[q].w, 0.f);
            }
        }
        __syncthreads();

        // ---------------- Phase 2 ----------------
        {
            uint64_t acc01[4], acc23[4];
#pragma unroll
            for (int j = 0; j < 4; j++) {
                float bv = b2s[j0 + j];
                uint64_t bb;
                asm("mov.b64 %0, {%1, %1};" : "=l"(bb) : "f"(bv));
                acc01[j] = bb; acc23[j] = bb;
            }
            uint32_t za = z1b + eg * 16;
            uint32_t wa = w2b + j0 * 8;
#pragma unroll 16
            for (int k = 0; k < HDIM; k++) {
                uint64_t z01, z23, w0, w1, w2v, w3v;
                asm("ld.shared.v2.b64 {%0,%1}, [%2];"
                    : "=l"(z01), "=l"(z23) : "r"(za + k * (SP1 * 4)));
                asm("ld.shared.v2.b64 {%0,%1}, [%2];"
                    : "=l"(w0), "=l"(w1) : "r"(wa + k * 256));
                asm("ld.shared.v2.b64 {%0,%1}, [%2];"
                    : "=l"(w2v), "=l"(w3v) : "r"(wa + k * 256 + 16));
                asm("fma.rn.f32x2 %0, %1, %2, %0;" : "+l"(acc01[0]) : "l"(z01), "l"(w0));
                asm("fma.rn.f32x2 %0, %1, %2, %0;" : "+l"(acc23[0]) : "l"(z23), "l"(w0));
                asm("fma.rn.f32x2 %0, %1, %2, %0;" : "+l"(acc01[1]) : "l"(z01), "l"(w1));
                asm("fma.rn.f32x2 %0, %1, %2, %0;" : "+l"(acc23[1]) : "l"(z23), "l"(w1));
                asm("fma.rn.f32x2 %0, %1, %2, %0;" : "+l"(acc01[2]) : "l"(z01), "l"(w2v));
                asm("fma.rn.f32x2 %0, %1, %2, %0;" : "+l"(acc23[2]) : "l"(z23), "l"(w2v));
                asm("fma.rn.f32x2 %0, %1, %2, %0;" : "+l"(acc01[3]) : "l"(z01), "l"(w3v));
                asm("fma.rn.f32x2 %0, %1, %2, %0;" : "+l"(acc23[3]) : "l"(z23), "l"(w3v));
            }
            float v0[4], v1[4], v2[4], v3[4];
#pragma unroll
            for (int j = 0; j < 4; j++) {
                float lo, hi;
                asm("mov.b64 {%0,%1}, %2;" : "=f"(lo), "=f"(hi) : "l"(acc01[j]));
                v0[j] = fmaxf(lo, 0.f); v1[j] = fmaxf(hi, 0.f);
                asm("mov.b64 {%0,%1}, %2;" : "=f"(lo), "=f"(hi) : "l"(acc23[j]));
                v2[j] = fmaxf(lo, 0.f); v3[j] = fmaxf(hi, 0.f);
            }
            int e0 = eg * 4;
            *(float4*)&z2s[(e0 + 0) * SP2 + j0] = make_float4(v0[0], v0[1], v0[2], v0[3]);
            *(float4*)&z2s[(e0 + 1) * SP2 + j0] = make_float4(v1[0], v1[1], v1[2], v1[3]);
            *(float4*)&z2s[(e0 + 2) * SP2 + j0] = make_float4(v2[0], v2[1], v2[2], v2[3]);
            *(float4*)&z2s[(e0 + 3) * SP2 + j0] = make_float4(v3[0], v3[1], v3[2], v3[3]);
        }
        __syncthreads();

        // ---------------- Phase 3 ----------------
        {
            int jo = hf * 5;
            float acc[5];
#pragma unroll
            for (int j = 0; j < 5; j++) acc[j] = b3s[jo + j];
            const float4* z2v = (const float4*)&z2s[el * SP2];
#pragma unroll
            for (int k4 = 0; k4 < 8; k4++) {
                float4 z = z2v[k4];
#pragma unroll
                for (int j = 0; j < 5; j++) {
                    float4 w = *(const float4*)&W3ts[(jo + j) * 32 + k4 * 4];
                    acc[j] = fmaf(z.x, w.x, acc[j]);
                    acc[j] = fmaf(z.y, w.y, acc[j]);
                    acc[j] = fmaf(z.z, w.z, acc[j]);
                    acc[j] = fmaf(z.w, w.w, acc[j]);
                }
            }
            float* op = out + (size_t)(ebase + el) * NCLS + jo;
#pragma unroll
            for (int j = 0; j < 5; j++) op[j] = acc[j];
        }
        __syncthreads();
    }
}

// ---------------------------------------------------------------------------
extern "C" void kernel_launch(void* const* d_in, const int* in_sizes, int n_in,
                              void* d_out, int out_size)
{
    const float* x  = (const float*)d_in[0];
    const int*   ei = (const int*)  d_in[1];
    const float* ea = (const float*)d_in[2];
    const float* Wn = (const float*)d_in[3];
    const float* bn = (const float*)d_in[4];
    const float* Wc = (const float*)d_in[5];
    const float* bc = (const float*)d_in[6];
    const float* W1 = (const float*)d_in[7];
    const float* b1 = (const float*)d_in[8];
    const float* W2 = (const float*)d_in[9];
    const float* b2 = (const float*)d_in[10];
    const float* W3 = (const float*)d_in[11];
    const float* b3 = (const float*)d_in[12];
    const int* src = ei;
    const int* dst = ei + NEDGES;
    float* out = (float*)d_out;

    const int NH_BLKS = (NNODES * HDIM) / 256;
    const int N_BLKS  = (NNODES + 255) / 256;
    const int E_BLKS  = NEDGES / 256;
    const int W_BLKS  = (NNODES * 32 + 255) / 256;   // warp-per-node grid

    // CSR build (also yields dinv)
    zero_deg_kernel<<<N_BLKS, 256>>>();
    hist_kernel<<<E_BLKS, 256>>>(dst);
    scan_kernel<<<1, 1024>>>();
    fill_kernel<<<E_BLKS, 256>>>(src, dst);

    // encoder
    encoder_kernel<<<NH_BLKS, 256>>>(x, Wn, bn);

    // 3 GCN layers: transform + atomic-free gather (finish fused)
    for (int l = 0; l < 3; l++) {
        gcn_transform_kernel<<<NNODES / 4, 256>>>(Wc + l * HDIM * HDIM);
        gcn_gather_kernel<<<W_BLKS, 256>>>(bc + l * HDIM);
    }

    pq_kernel<<<NNODES / 4, 256>>>(W1, b1);

    edge_mlp_v2_kernel<<<NEDGES / (TILE_E * NTILE), 128>>>(
        src, dst, ea, W1, W2, b2, W3, b3, out);
}

// round 12
// speedup vs baseline: 1.9182x; 1.0714x over previous
#include <cuda_runtime.h>
#include <cstdint>
#include <cstddef>

#define NNODES 50000
#define NEDGES 1600000
#define HDIM   64
#define FNODE  8
#define FEDGE  8
#define NCLS   10

// ---------------- scratch (device globals; no allocation allowed) ----------
__device__ __align__(16) float g_h   [NNODES * HDIM];
__device__ __align__(16) float g_g   [NNODES * HDIM];
__device__ __align__(16) float g_dinv[NNODES];
__device__ __align__(16) float g_P   [NNODES * HDIM];
__device__ __align__(16) float g_Q   [NNODES * HDIM];
__device__ int  g_deg[NNODES];
__device__ int  g_off[NNODES + 1];
__device__ int  g_cur[NNODES];
__device__ int  g_csr[NEDGES];          // src indices grouped by dst

// ---------------- node encoder: h = x @ W_node + b_node --------------------
__global__ void __launch_bounds__(256) encoder_kernel(
    const float* __restrict__ x, const float* __restrict__ Wn,
    const float* __restrict__ bn)
{
    __shared__ float Ws[FNODE * HDIM];
    int tid = threadIdx.x;
    for (int i = tid; i < FNODE * HDIM; i += 256) Ws[i] = Wn[i];
    __syncthreads();
    int t = blockIdx.x * 256 + tid;
    int n = t >> 6, j = t & 63;
    float s = bn[j];
#pragma unroll
    for (int k = 0; k < FNODE; k++)
        s = fmaf(x[n * FNODE + k], Ws[k * HDIM + j], s);
    g_h[t] = s;
}

// ---------------- CSR build ------------------------------------------------
__global__ void zero_deg_kernel() {
    int n = blockIdx.x * 256 + threadIdx.x;
    if (n < NNODES) g_deg[n] = 0;
}
__global__ void hist_kernel(const int* __restrict__ dst) {
    int e = blockIdx.x * 256 + threadIdx.x;
    if (e < NEDGES) atomicAdd(&g_deg[dst[e]], 1);
}
// single-block exclusive scan over g_deg -> g_off/g_cur; also dinv = rsqrt(deg+1)
__global__ void __launch_bounds__(1024) scan_kernel() {
    __shared__ int carry;
    __shared__ int warp_tot[32];
    int tid = threadIdx.x, lane = tid & 31, wid = tid >> 5;
    if (tid == 0) carry = 0;
    __syncthreads();
    for (int base = 0; base < NNODES; base += 1024) {
        int n = base + tid;
        int v = (n < NNODES) ? g_deg[n] : 0;
        int x = v;
#pragma unroll
        for (int o = 1; o < 32; o <<= 1) {
            int y = __shfl_up_sync(0xffffffffu, x, o);
            if (lane >= o) x += y;
        }
        if (lane == 31) warp_tot[wid] = x;
        __syncthreads();
        if (wid == 0) {
            int t = warp_tot[lane];
#pragma unroll
            for (int o = 1; o < 32; o <<= 1) {
                int y = __shfl_up_sync(0xffffffffu, t, o);
                if (lane >= o) t += y;
            }
            warp_tot[lane] = t;
        }
        __syncthreads();
        int incl = x + (wid > 0 ? warp_tot[wid - 1] : 0) + carry;
        if (n < NNODES) {
            int excl = incl - v;
            g_off[n] = excl;
            g_cur[n] = excl;
            g_dinv[n] = rsqrtf((float)(v + 1));   // +1 self-loop
        }
        __syncthreads();
        if (tid == 1023) carry = incl;
        __syncthreads();
    }
    if (tid == 0) g_off[NNODES] = NEDGES;
}
__global__ void fill_kernel(const int* __restrict__ src, const int* __restrict__ dst) {
    int e = blockIdx.x * 256 + threadIdx.x;
    if (e < NEDGES) {
        int pos = atomicAdd(&g_cur[dst[e]], 1);
        g_csr[pos] = src[e];
    }
}

// ------------- GCN transform: g = (h @ W) * dinv ---------------------------
__global__ void __launch_bounds__(256) gcn_transform_kernel(
    const float* __restrict__ W)
{
    __shared__ float Ws[HDIM * HDIM];
    __shared__ float hs[4 * HDIM];
    int tid = threadIdx.x;
#pragma unroll 4
    for (int i = tid; i < HDIM * HDIM; i += 256) Ws[i] = W[i];
    int n0 = blockIdx.x * 4;
    hs[tid] = g_h[n0 * HDIM + tid];
    __syncthreads();
    int nn = tid >> 6, j = tid & 63;
    float s = 0.f;
#pragma unroll
    for (int k = 0; k < HDIM; k++)
        s = fmaf(hs[nn * HDIM + k], Ws[k * HDIM + j], s);
    int n = n0 + nn;
    g_g[n * HDIM + j] = s * g_dinv[n];
}

// ------------- GCN gather+finish: warp per node, no atomics ----------------
__global__ void __launch_bounds__(256) gcn_gather_kernel(
    const float* __restrict__ b)
{
    int n = (blockIdx.x * 256 + threadIdx.x) >> 5;
    if (n >= NNODES) return;
    int lane = threadIdx.x & 31;
    int beg = g_off[n], end = g_off[n + 1];
    float a0 = g_g[(size_t)n * HDIM + lane];
    float a1 = g_g[(size_t)n * HDIM + 32 + lane];
    int j = beg;
    for (; j + 4 <= end; j += 4) {
        int s0 = g_csr[j], s1 = g_csr[j + 1], s2 = g_csr[j + 2], s3 = g_csr[j + 3];
        float v00 = g_g[(size_t)s0 * HDIM + lane];
        float v01 = g_g[(size_t)s0 * HDIM + 32 + lane];
        float v10 = g_g[(size_t)s1 * HDIM + lane];
        float v11 = g_g[(size_t)s1 * HDIM + 32 + lane];
        float v20 = g_g[(size_t)s2 * HDIM + lane];
        float v21 = g_g[(size_t)s2 * HDIM + 32 + lane];
        float v30 = g_g[(size_t)s3 * HDIM + lane];
        float v31 = g_g[(size_t)s3 * HDIM + 32 + lane];
        a0 += v00 + v10 + v20 + v30;
        a1 += v01 + v11 + v21 + v31;
    }
    for (; j < end; j++) {
        int s = g_csr[j];
        a0 += g_g[(size_t)s * HDIM + lane];
        a1 += g_g[(size_t)s * HDIM + 32 + lane];
    }
    float di = g_dinv[n];
    g_h[(size_t)n * HDIM + lane]      = fmaxf(fmaf(di, a0, b[lane]),      0.f);
    g_h[(size_t)n * HDIM + 32 + lane] = fmaxf(fmaf(di, a1, b[lane + 32]), 0.f);
}

// ------------- P = h@W1a + b1 ; Q = h@W1b ----------------------------------
__global__ void __launch_bounds__(256) pq_kernel(
    const float* __restrict__ W1, const float* __restrict__ b1)
{
    __shared__ float Ws[2 * HDIM * HDIM];
    __shared__ float hs[4 * HDIM];
    int tid = threadIdx.x;
#pragma unroll 8
    for (int i = tid; i < 2 * HDIM * HDIM; i += 256) Ws[i] = W1[i];
    int n0 = blockIdx.x * 4;
    hs[tid] = g_h[n0 * HDIM + tid];
    __syncthreads();
    int nn = tid >> 6, j = tid & 63;
    float p = b1[j], q = 0.f;
#pragma unroll
    for (int k = 0; k < HDIM; k++) {
        float hv = hs[nn * HDIM + k];
        p = fmaf(hv, Ws[k * HDIM + j], p);
        q = fmaf(hv, Ws[(HDIM + k) * HDIM + j], q);
    }
    int n = n0 + nn;
    g_P[n * HDIM + j] = p;
    g_Q[n * HDIM + j] = q;
}

// ======================= edge MLP v3: coalesced P/Q gather ==================
#define TILE_E 64
#define NTILE  8
#define SP1    68
#define SP2    36

__global__ void __launch_bounds__(128) edge_mlp_v3_kernel(
    const int*   __restrict__ src, const int* __restrict__ dst,
    const float* __restrict__ ea,
    const float* __restrict__ W1,
    const float* __restrict__ W2,  const float* __restrict__ b2,
    const float* __restrict__ W3,  const float* __restrict__ b3,
    float*       __restrict__ out)
{
    __shared__ float  z1p[HDIM * SP1];
    __shared__ float  z2s[TILE_E * SP2];
    __shared__ float2 W2d[HDIM * 32];
    __shared__ float  W1cs[FEDGE * HDIM];
    __shared__ float  W3ts[NCLS * 32];
    __shared__ float  b2s[32];
    __shared__ float  b3s[NCLS];

    int tid = threadIdx.x;

    for (int i = tid; i < FEDGE * HDIM; i += 128) W1cs[i] = W1[2 * HDIM * HDIM + i];
    for (int i = tid; i < HDIM * 32; i += 128) {
        float w = W2[i];
        W2d[i] = make_float2(w, w);
    }
    for (int i = tid; i < NCLS * 32; i += 128) {
        int j = i >> 5, k = i & 31;
        W3ts[i] = W3[k * NCLS + j];
    }
    if (tid < 32)  b2s[tid] = b2[tid];
    if (tid < NCLS) b3s[tid] = b3[tid];
    __syncthreads();

    uint32_t z1b = (uint32_t)__cvta_generic_to_shared(z1p);
    uint32_t w2b = (uint32_t)__cvta_generic_to_shared(W2d);

    int el = tid >> 1;
    int hf = tid & 1;
    int eg = tid & 15;
    int cg = tid >> 4;
    int j0 = cg * 4;
    int lane = tid & 31, wrp = tid >> 5;

#pragma unroll 1
    for (int it = 0; it < NTILE; ++it) {
        int ebase = (blockIdx.x * NTILE + it) * TILE_E;

        // -------- Phase 1a: z1p[k][e] = attr @ W1c  (raw) ------------------
        {
            int e = ebase + el;
            const float4* eap = (const float4*)(ea + (size_t)e * FEDGE);
            float4 a0 = eap[0], a1 = eap[1];
            float av[8] = {a0.x, a0.y, a0.z, a0.w, a1.x, a1.y, a1.z, a1.w};
            const float4* W1c4 = (const float4*)W1cs;
            float4 acc[8];
#pragma unroll
            for (int q = 0; q < 8; q++) acc[q] = make_float4(0.f, 0.f, 0.f, 0.f);
#pragma unroll
            for (int k = 0; k < FEDGE; k++) {
                float ak = av[k];
#pragma unroll
                for (int q = 0; q < 8; q++) {
                    float4 w = W1c4[k * 16 + hf * 8 + q];
                    acc[q].x = fmaf(ak, w.x, acc[q].x);
                    acc[q].y = fmaf(ak, w.y, acc[q].y);
                    acc[q].z = fmaf(ak, w.z, acc[q].z);
                    acc[q].w = fmaf(ak, w.w, acc[q].w);
                }
            }
#pragma unroll
            for (int q = 0; q < 8; q++) {
                int k = hf * 32 + q * 4;
                z1p[(k + 0) * SP1 + el] = acc[q].x;
                z1p[(k + 1) * SP1 + el] = acc[q].y;
                z1p[(k + 2) * SP1 + el] = acc[q].z;
                z1p[(k + 3) * SP1 + el] = acc[q].w;
            }
        }
        __syncthreads();

        // -------- Phase 1b: z1p += P[s]+Q[d]; relu (coalesced) -------------
        {
#pragma unroll
            for (int i = 0; i < 8; i++) {
                int e = wrp * 4 + (lane >> 3) + (i >> 1) * 16;   // 0..63
                int c = (lane & 7) + (i & 1) * 8;                // chunk 0..15
                int ge = ebase + e;
                int s = src[ge], d = dst[ge];
                float4 p = *(const float4*)(g_P + (size_t)s * HDIM + c * 4);
                float4 q = *(const float4*)(g_Q + (size_t)d * HDIM + c * 4);
                float* zp = &z1p[(c * 4) * SP1 + e];
                zp[0]       = fmaxf(zp[0]       + p.x + q.x, 0.f);
                zp[SP1]     = fmaxf(zp[SP1]     + p.y + q.y, 0.f);
                zp[2 * SP1] = fmaxf(zp[2 * SP1] + p.z + q.z, 0.f);
                zp[3 * SP1] = fmaxf(zp[3 * SP1] + p.w + q.w, 0.f);
            }
        }
        __syncthreads();

        // ---------------- Phase 2 ----------------
        {
            uint64_t acc01[4], acc23[4];
#pragma unroll
            for (int j = 0; j < 4; j++) {
                float bv = b2s[j0 + j];
                uint64_t bb;
                asm("mov.b64 %0, {%1, %1};" : "=l"(bb) : "f"(bv));
                acc01[j] = bb; acc23[j] = bb;
            }
            uint32_t za = z1b + eg * 16;
            uint32_t wa = w2b + j0 * 8;
#pragma unroll 16
            for (int k = 0; k < HDIM; k++) {
                uint64_t z01, z23, w0, w1, w2v, w3v;
                asm("ld.shared.v2.b64 {%0,%1}, [%2];"
                    : "=l"(z01), "=l"(z23) : "r"(za + k * (SP1 * 4)));
                asm("ld.shared.v2.b64 {%0,%1}, [%2];"
                    : "=l"(w0), "=l"(w1) : "r"(wa + k * 256));
                asm("ld.shared.v2.b64 {%0,%1}, [%2];"
                    : "=l"(w2v), "=l"(w3v) : "r"(wa + k * 256 + 16));
                asm("fma.rn.f32x2 %0, %1, %2, %0;" : "+l"(acc01[0]) : "l"(z01), "l"(w0));
                asm("fma.rn.f32x2 %0, %1, %2, %0;" : "+l"(acc23[0]) : "l"(z23), "l"(w0));
                asm("fma.rn.f32x2 %0, %1, %2, %0;" : "+l"(acc01[1]) : "l"(z01), "l"(w1));
                asm("fma.rn.f32x2 %0, %1, %2, %0;" : "+l"(acc23[1]) : "l"(z23), "l"(w1));
                asm("fma.rn.f32x2 %0, %1, %2, %0;" : "+l"(acc01[2]) : "l"(z01), "l"(w2v));
                asm("fma.rn.f32x2 %0, %1, %2, %0;" : "+l"(acc23[2]) : "l"(z23), "l"(w2v));
                asm("fma.rn.f32x2 %0, %1, %2, %0;" : "+l"(acc01[3]) : "l"(z01), "l"(w3v));
                asm("fma.rn.f32x2 %0, %1, %2, %0;" : "+l"(acc23[3]) : "l"(z23), "l"(w3v));
            }
            float v0[4], v1[4], v2[4], v3[4];
#pragma unroll
            for (int j = 0; j < 4; j++) {
                float lo, hi;
                asm("mov.b64 {%0,%1}, %2;" : "=f"(lo), "=f"(hi) : "l"(acc01[j]));
                v0[j] = fmaxf(lo, 0.f); v1[j] = fmaxf(hi, 0.f);
                asm("mov.b64 {%0,%1}, %2;" : "=f"(lo), "=f"(hi) : "l"(acc23[j]));
                v2[j] = fmaxf(lo, 0.f); v3[j] = fmaxf(hi, 0.f);
            }
            int e0 = eg * 4;
            *(float4*)&z2s[(e0 + 0) * SP2 + j0] = make_float4(v0[0], v0[1], v0[2], v0[3]);
            *(float4*)&z2s[(e0 + 1) * SP2 + j0] = make_float4(v1[0], v1[1], v1[2], v1[3]);
            *(float4*)&z2s[(e0 + 2) * SP2 + j0] = make_float4(v2[0], v2[1], v2[2], v2[3]);
            *(float4*)&z2s[(e0 + 3) * SP2 + j0] = make_float4(v3[0], v3[1], v3[2], v3[3]);
        }
        __syncthreads();

        // ---------------- Phase 3 ----------------
        {
            int jo = hf * 5;
            float acc[5];
#pragma unroll
            for (int j = 0; j < 5; j++) acc[j] = b3s[jo + j];
            const float4* z2v = (const float4*)&z2s[el * SP2];
#pragma unroll
            for (int k4 = 0; k4 < 8; k4++) {
                float4 z = z2v[k4];
#pragma unroll
                for (int j = 0; j < 5; j++) {
                    float4 w = *(const float4*)&W3ts[(jo + j) * 32 + k4 * 4];
                    acc[j] = fmaf(z.x, w.x, acc[j]);
                    acc[j] = fmaf(z.y, w.y, acc[j]);
                    acc[j] = fmaf(z.z, w.z, acc[j]);
                    acc[j] = fmaf(z.w, w.w, acc[j]);
                }
            }
            float* op = out + (size_t)(ebase + el) * NCLS + jo;
#pragma unroll
            for (int j = 0; j < 5; j++) op[j] = acc[j];
        }
        __syncthreads();
    }
}

// ---------------------------------------------------------------------------
extern "C" void kernel_launch(void* const* d_in, const int* in_sizes, int n_in,
                              void* d_out, int out_size)
{
    const float* x  = (const float*)d_in[0];
    const int*   ei = (const int*)  d_in[1];
    const float* ea = (const float*)d_in[2];
    const float* Wn = (const float*)d_in[3];
    const float* bn = (const float*)d_in[4];
    const float* Wc = (const float*)d_in[5];
    const float* bc = (const float*)d_in[6];
    const float* W1 = (const float*)d_in[7];
    const float* b1 = (const float*)d_in[8];
    const float* W2 = (const float*)d_in[9];
    const float* b2 = (const float*)d_in[10];
    const float* W3 = (const float*)d_in[11];
    const float* b3 = (const float*)d_in[12];
    const int* src = ei;
    const int* dst = ei + NEDGES;
    float* out = (float*)d_out;

    const int NH_BLKS = (NNODES * HDIM) / 256;
    const int N_BLKS  = (NNODES + 255) / 256;
    const int E_BLKS  = NEDGES / 256;
    const int W_BLKS  = (NNODES * 32 + 255) / 256;

    // CSR build (also yields dinv)
    zero_deg_kernel<<<N_BLKS, 256>>>();
    hist_kernel<<<E_BLKS, 256>>>(dst);
    scan_kernel<<<1, 1024>>>();
    fill_kernel<<<E_BLKS, 256>>>(src, dst);

    // encoder
    encoder_kernel<<<NH_BLKS, 256>>>(x, Wn, bn);

    // 3 GCN layers
    for (int l = 0; l < 3; l++) {
        gcn_transform_kernel<<<NNODES / 4, 256>>>(Wc + l * HDIM * HDIM);
        gcn_gather_kernel<<<W_BLKS, 256>>>(bc + l * HDIM);
    }

    pq_kernel<<<NNODES / 4, 256>>>(W1, b1);

    edge_mlp_v3_kernel<<<NEDGES / (TILE_E * NTILE), 128>>>(
        src, dst, ea, W1, W2, b2, W3, b3, out);
}

// round 13
// speedup vs baseline: 1.9615x; 1.0226x over previous
#include <cuda_runtime.h>
#include <cstdint>
#include <cstddef>

#define NNODES 50000
#define NEDGES 1600000
#define HDIM   64
#define FNODE  8
#define FEDGE  8
#define NCLS   10

// ---------------- scratch (device globals; no allocation allowed) ----------
__device__ __align__(16) float g_h   [NNODES * HDIM];
__device__ __align__(16) float g_g   [NNODES * HDIM];
__device__ __align__(16) float g_dinv[NNODES];
__device__ __align__(16) float g_P   [NNODES * HDIM];
__device__ __align__(16) float g_Q   [NNODES * HDIM];
__device__ int  g_deg[NNODES];
__device__ int  g_off[NNODES + 1];
__device__ int  g_cur[NNODES];
__device__ int  g_csr[NEDGES];          // src indices grouped by dst

// ---------------- node encoder: h = x @ W_node + b_node --------------------
__global__ void __launch_bounds__(256) encoder_kernel(
    const float* __restrict__ x, const float* __restrict__ Wn,
    const float* __restrict__ bn)
{
    __shared__ float Ws[FNODE * HDIM];
    int tid = threadIdx.x;
    for (int i = tid; i < FNODE * HDIM; i += 256) Ws[i] = Wn[i];
    __syncthreads();
    int t = blockIdx.x * 256 + tid;
    int n = t >> 6, j = t & 63;
    float s = bn[j];
#pragma unroll
    for (int k = 0; k < FNODE; k++)
        s = fmaf(x[n * FNODE + k], Ws[k * HDIM + j], s);
    g_h[t] = s;
}

// ---------------- CSR build ------------------------------------------------
__global__ void zero_deg_kernel() {
    int n = blockIdx.x * 256 + threadIdx.x;
    if (n < NNODES) g_deg[n] = 0;
}
__global__ void hist_kernel(const int* __restrict__ dst) {
    int e = blockIdx.x * 256 + threadIdx.x;
    if (e < NEDGES) atomicAdd(&g_deg[dst[e]], 1);
}
__global__ void __launch_bounds__(1024) scan_kernel() {
    __shared__ int carry;
    __shared__ int warp_tot[32];
    int tid = threadIdx.x, lane = tid & 31, wid = tid >> 5;
    if (tid == 0) carry = 0;
    __syncthreads();
    for (int base = 0; base < NNODES; base += 1024) {
        int n = base + tid;
        int v = (n < NNODES) ? g_deg[n] : 0;
        int x = v;
#pragma unroll
        for (int o = 1; o < 32; o <<= 1) {
            int y = __shfl_up_sync(0xffffffffu, x, o);
            if (lane >= o) x += y;
        }
        if (lane == 31) warp_tot[wid] = x;
        __syncthreads();
        if (wid == 0) {
            int t = warp_tot[lane];
#pragma unroll
            for (int o = 1; o < 32; o <<= 1) {
                int y = __shfl_up_sync(0xffffffffu, t, o);
                if (lane >= o) t += y;
            }
            warp_tot[lane] = t;
        }
        __syncthreads();
        int incl = x + (wid > 0 ? warp_tot[wid - 1] : 0) + carry;
        if (n < NNODES) {
            int excl = incl - v;
            g_off[n] = excl;
            g_cur[n] = excl;
            g_dinv[n] = rsqrtf((float)(v + 1));   // +1 self-loop
        }
        __syncthreads();
        if (tid == 1023) carry = incl;
        __syncthreads();
    }
    if (tid == 0) g_off[NNODES] = NEDGES;
}
__global__ void fill_kernel(const int* __restrict__ src, const int* __restrict__ dst) {
    int e = blockIdx.x * 256 + threadIdx.x;
    if (e < NEDGES) {
        int pos = atomicAdd(&g_cur[dst[e]], 1);
        g_csr[pos] = src[e];
    }
}

// ------------- GCN transform: g = (h @ W) * dinv ---------------------------
__global__ void __launch_bounds__(256) gcn_transform_kernel(
    const float* __restrict__ W)
{
    __shared__ float Ws[HDIM * HDIM];
    __shared__ float hs[4 * HDIM];
    int tid = threadIdx.x;
#pragma unroll 4
    for (int i = tid; i < HDIM * HDIM; i += 256) Ws[i] = W[i];
    int n0 = blockIdx.x * 4;
    hs[tid] = g_h[n0 * HDIM + tid];
    __syncthreads();
    int nn = tid >> 6, j = tid & 63;
    float s = 0.f;
#pragma unroll
    for (int k = 0; k < HDIM; k++)
        s = fmaf(hs[nn * HDIM + k], Ws[k * HDIM + j], s);
    int n = n0 + nn;
    g_g[n * HDIM + j] = s * g_dinv[n];
}

// ------------- GCN gather+finish: warp per node, no atomics ----------------
__global__ void __launch_bounds__(256) gcn_gather_kernel(
    const float* __restrict__ b)
{
    int n = (blockIdx.x * 256 + threadIdx.x) >> 5;
    if (n >= NNODES) return;
    int lane = threadIdx.x & 31;
    int beg = g_off[n], end = g_off[n + 1];
    float a0 = g_g[(size_t)n * HDIM + lane];
    float a1 = g_g[(size_t)n * HDIM + 32 + lane];
    int j = beg;
    for (; j + 4 <= end; j += 4) {
        int s0 = g_csr[j], s1 = g_csr[j + 1], s2 = g_csr[j + 2], s3 = g_csr[j + 3];
        float v00 = g_g[(size_t)s0 * HDIM + lane];
        float v01 = g_g[(size_t)s0 * HDIM + 32 + lane];
        float v10 = g_g[(size_t)s1 * HDIM + lane];
        float v11 = g_g[(size_t)s1 * HDIM + 32 + lane];
        float v20 = g_g[(size_t)s2 * HDIM + lane];
        float v21 = g_g[(size_t)s2 * HDIM + 32 + lane];
        float v30 = g_g[(size_t)s3 * HDIM + lane];
        float v31 = g_g[(size_t)s3 * HDIM + 32 + lane];
        a0 += v00 + v10 + v20 + v30;
        a1 += v01 + v11 + v21 + v31;
    }
    for (; j < end; j++) {
        int s = g_csr[j];
        a0 += g_g[(size_t)s * HDIM + lane];
        a1 += g_g[(size_t)s * HDIM + 32 + lane];
    }
    float di = g_dinv[n];
    g_h[(size_t)n * HDIM + lane]      = fmaxf(fmaf(di, a0, b[lane]),      0.f);
    g_h[(size_t)n * HDIM + 32 + lane] = fmaxf(fmaf(di, a1, b[lane + 32]), 0.f);
}

// ------------- P = h@W1a + b1 ; Q = h@W1b ----------------------------------
__global__ void __launch_bounds__(256) pq_kernel(
    const float* __restrict__ W1, const float* __restrict__ b1)
{
    __shared__ float Ws[2 * HDIM * HDIM];
    __shared__ float hs[4 * HDIM];
    int tid = threadIdx.x;
#pragma unroll 8
    for (int i = tid; i < 2 * HDIM * HDIM; i += 256) Ws[i] = W1[i];
    int n0 = blockIdx.x * 4;
    hs[tid] = g_h[n0 * HDIM + tid];
    __syncthreads();
    int nn = tid >> 6, j = tid & 63;
    float p = b1[j], q = 0.f;
#pragma unroll
    for (int k = 0; k < HDIM; k++) {
        float hv = hs[nn * HDIM + k];
        p = fmaf(hv, Ws[k * HDIM + j], p);
        q = fmaf(hv, Ws[(HDIM + k) * HDIM + j], q);
    }
    int n = n0 + nn;
    g_P[n * HDIM + j] = p;
    g_Q[n * HDIM + j] = q;
}

// ========= edge MLP v4: 256 threads, two independent 128-thread halves =====
// Each half runs the v3 pipeline on its own tile stream, with its own
// z1p/z2s buffers and a named barrier. Weights staged once, shared.
// Dynamic smem (73216 B) -> 3 blocks/SM = 24 warps/SM.
#define TILE_E   64
#define TPH      5          // tiles per half; block covers 2*TPH tiles
#define SP1      68
#define SP2      36
// byte offsets in dynamic smem
#define OFF_W2D  0                      // float2[64*32]  = 16384
#define OFF_W1C  16384                  // float[8*64]    =  2048
#define OFF_W3T  18432                  // float[10*32]   =  1280
#define OFF_B2   19712                  // float[32]      =   128
#define OFF_B3   19840                  // float[16]      =    64 (padded)
#define OFF_HALF 19968                  // per-half region start (128-aligned)
#define HALF_SZ  26624                  // z1p 17408 + z2s 9216
#define SMEM_V4  (OFF_HALF + 2 * HALF_SZ)   // 73216

__global__ void __launch_bounds__(256, 3) edge_mlp_v4_kernel(
    const int*   __restrict__ src, const int* __restrict__ dst,
    const float* __restrict__ ea,
    const float* __restrict__ W1,
    const float* __restrict__ W2,  const float* __restrict__ b2,
    const float* __restrict__ W3,  const float* __restrict__ b3,
    float*       __restrict__ out)
{
    extern __shared__ __align__(16) char sm[];
    float2* W2d  = (float2*)(sm + OFF_W2D);
    float*  W1cs = (float*)(sm + OFF_W1C);
    float*  W3ts = (float*)(sm + OFF_W3T);
    float*  b2s  = (float*)(sm + OFF_B2);
    float*  b3s  = (float*)(sm + OFF_B3);

    int tid = threadIdx.x;
    int h   = tid >> 7;                 // half 0 / 1
    int t128 = tid & 127;

    float* z1p = (float*)(sm + OFF_HALF + h * HALF_SZ);
    float* z2s = z1p + HDIM * SP1;

    // ---- stage weights once (all 256 threads) ----
    for (int i = tid; i < HDIM * 32; i += 256) {
        float w = W2[i];
        W2d[i] = make_float2(w, w);
    }
    for (int i = tid; i < FEDGE * HDIM; i += 256) W1cs[i] = W1[2 * HDIM * HDIM + i];
    for (int i = tid; i < NCLS * 32; i += 256) {
        int j = i >> 5, k = i & 31;
        W3ts[i] = W3[k * NCLS + j];
    }
    if (tid < 32)   b2s[tid] = b2[tid];
    if (tid < NCLS) b3s[tid] = b3[tid];
    __syncthreads();

    uint32_t z1b = (uint32_t)__cvta_generic_to_shared(z1p);
    uint32_t w2b = (uint32_t)__cvta_generic_to_shared(W2d);

    int el = t128 >> 1;
    int hf = t128 & 1;
    int eg = t128 & 15;
    int cg = (t128 >> 4) & 7;
    int j0 = cg * 4;
    int lane = t128 & 31, wrp = t128 >> 5;
    int bar = h + 1;

#pragma unroll 1
    for (int it = 0; it < TPH; ++it) {
        int ebase = (blockIdx.x * (2 * TPH) + h * TPH + it) * TILE_E;

        // -------- Phase 1a: z1p[k][e] = attr @ W1c  (raw) ------------------
        {
            int e = ebase + el;
            const float4* eap = (const float4*)(ea + (size_t)e * FEDGE);
            float4 a0 = eap[0], a1 = eap[1];
            float av[8] = {a0.x, a0.y, a0.z, a0.w, a1.x, a1.y, a1.z, a1.w};
            const float4* W1c4 = (const float4*)W1cs;
            float4 acc[8];
#pragma unroll
            for (int q = 0; q < 8; q++) acc[q] = make_float4(0.f, 0.f, 0.f, 0.f);
#pragma unroll
            for (int k = 0; k < FEDGE; k++) {
                float ak = av[k];
#pragma unroll
                for (int q = 0; q < 8; q++) {
                    float4 w = W1c4[k * 16 + hf * 8 + q];
                    acc[q].x = fmaf(ak, w.x, acc[q].x);
                    acc[q].y = fmaf(ak, w.y, acc[q].y);
                    acc[q].z = fmaf(ak, w.z, acc[q].z);
                    acc[q].w = fmaf(ak, w.w, acc[q].w);
                }
            }
#pragma unroll
            for (int q = 0; q < 8; q++) {
                int k = hf * 32 + q * 4;
                z1p[(k + 0) * SP1 + el] = acc[q].x;
                z1p[(k + 1) * SP1 + el] = acc[q].y;
                z1p[(k + 2) * SP1 + el] = acc[q].z;
                z1p[(k + 3) * SP1 + el] = acc[q].w;
            }
        }
        asm volatile("bar.sync %0, 128;" :: "r"(bar) : "memory");

        // -------- Phase 1b: z1p += P[s]+Q[d]; relu (coalesced) -------------
        {
#pragma unroll
            for (int i = 0; i < 8; i++) {
                int e = wrp * 4 + (lane >> 3) + (i >> 1) * 16;   // 0..63
                int c = (lane & 7) + (i & 1) * 8;                // chunk 0..15
                int ge = ebase + e;
                int s = src[ge], d = dst[ge];
                float4 p = *(const float4*)(g_P + (size_t)s * HDIM + c * 4);
                float4 q = *(const float4*)(g_Q + (size_t)d * HDIM + c * 4);
                float* zp = &z1p[(c * 4) * SP1 + e];
                zp[0]       = fmaxf(zp[0]       + p.x + q.x, 0.f);
                zp[SP1]     = fmaxf(zp[SP1]     + p.y + q.y, 0.f);
                zp[2 * SP1] = fmaxf(zp[2 * SP1] + p.z + q.z, 0.f);
                zp[3 * SP1] = fmaxf(zp[3 * SP1] + p.w + q.w, 0.f);
            }
        }
        asm volatile("bar.sync %0, 128;" :: "r"(bar) : "memory");

        // ---------------- Phase 2 ----------------
        {
            uint64_t acc01[4], acc23[4];
#pragma unroll
            for (int j = 0; j < 4; j++) {
                float bv = b2s[j0 + j];
                uint64_t bb;
                asm("mov.b64 %0, {%1, %1};" : "=l"(bb) : "f"(bv));
                acc01[j] = bb; acc23[j] = bb;
            }
            uint32_t za = z1b + eg * 16;
            uint32_t wa = w2b + j0 * 8;
#pragma unroll 16
            for (int k = 0; k < HDIM; k++) {
                uint64_t z01, z23, w0, w1, w2v, w3v;
                asm("ld.shared.v2.b64 {%0,%1}, [%2];"
                    : "=l"(z01), "=l"(z23) : "r"(za + k * (SP1 * 4)));
                asm("ld.shared.v2.b64 {%0,%1}, [%2];"
                    : "=l"(w0), "=l"(w1) : "r"(wa + k * 256));
                asm("ld.shared.v2.b64 {%0,%1}, [%2];"
                    : "=l"(w2v), "=l"(w3v) : "r"(wa + k * 256 + 16));
                asm("fma.rn.f32x2 %0, %1, %2, %0;" : "+l"(acc01[0]) : "l"(z01), "l"(w0));
                asm("fma.rn.f32x2 %0, %1, %2, %0;" : "+l"(acc23[0]) : "l"(z23), "l"(w0));
                asm("fma.rn.f32x2 %0, %1, %2, %0;" : "+l"(acc01[1]) : "l"(z01), "l"(w1));
                asm("fma.rn.f32x2 %0, %1, %2, %0;" : "+l"(acc23[1]) : "l"(z23), "l"(w1));
                asm("fma.rn.f32x2 %0, %1, %2, %0;" : "+l"(acc01[2]) : "l"(z01), "l"(w2v));
                asm("fma.rn.f32x2 %0, %1, %2, %0;" : "+l"(acc23[2]) : "l"(z23), "l"(w2v));
                asm("fma.rn.f32x2 %0, %1, %2, %0;" : "+l"(acc01[3]) : "l"(z01), "l"(w3v));
                asm("fma.rn.f32x2 %0, %1, %2, %0;" : "+l"(acc23[3]) : "l"(z23), "l"(w3v));
            }
            float v0[4], v1[4], v2[4], v3[4];
#pragma unroll
            for (int j = 0; j < 4; j++) {
                float lo, hi;
                asm("mov.b64 {%0,%1}, %2;" : "=f"(lo), "=f"(hi) : "l"(acc01[j]));
                v0[j] = fmaxf(lo, 0.f); v1[j] = fmaxf(hi, 0.f);
                asm("mov.b64 {%0,%1}, %2;" : "=f"(lo), "=f"(hi) : "l"(acc23[j]));
                v2[j] = fmaxf(lo, 0.f); v3[j] = fmaxf(hi, 0.f);
            }
            int e0 = eg * 4;
            *(float4*)&z2s[(e0 + 0) * SP2 + j0] = make_float4(v0[0], v0[1], v0[2], v0[3]);
            *(float4*)&z2s[(e0 + 1) * SP2 + j0] = make_float4(v1[0], v1[1], v1[2], v1[3]);
            *(float4*)&z2s[(e0 + 2) * SP2 + j0] = make_float4(v2[0], v2[1], v2[2], v2[3]);
            *(float4*)&z2s[(e0 + 3) * SP2 + j0] = make_float4(v3[0], v3[1], v3[2], v3[3]);
        }
        asm volatile("bar.sync %0, 128;" :: "r"(bar) : "memory");

        // ---------------- Phase 3 ----------------
        {
            int jo = hf * 5;
            float acc[5];
#pragma unroll
            for (int j = 0; j < 5; j++) acc[j] = b3s[jo + j];
            const float4* z2v = (const float4*)&z2s[el * SP2];
#pragma unroll
            for (int k4 = 0; k4 < 8; k4++) {
                float4 z = z2v[k4];
#pragma unroll
                for (int j = 0; j < 5; j++) {
                    float4 w = *(const float4*)&W3ts[(jo + j) * 32 + k4 * 4];
                    acc[j] = fmaf(z.x, w.x, acc[j]);
                    acc[j] = fmaf(z.y, w.y, acc[j]);
                    acc[j] = fmaf(z.z, w.z, acc[j]);
                    acc[j] = fmaf(z.w, w.w, acc[j]);
                }
            }
            float* op = out + (size_t)(ebase + el) * NCLS + jo;
#pragma unroll
            for (int j = 0; j < 5; j++) op[j] = acc[j];
        }
        asm volatile("bar.sync %0, 128;" :: "r"(bar) : "memory");
    }
}

// ---------------------------------------------------------------------------
extern "C" void kernel_launch(void* const* d_in, const int* in_sizes, int n_in,
                              void* d_out, int out_size)
{
    const float* x  = (const float*)d_in[0];
    const int*   ei = (const int*)  d_in[1];
    const float* ea = (const float*)d_in[2];
    const float* Wn = (const float*)d_in[3];
    const float* bn = (const float*)d_in[4];
    const float* Wc = (const float*)d_in[5];
    const float* bc = (const float*)d_in[6];
    const float* W1 = (const float*)d_in[7];
    const float* b1 = (const float*)d_in[8];
    const float* W2 = (const float*)d_in[9];
    const float* b2 = (const float*)d_in[10];
    const float* W3 = (const float*)d_in[11];
    const float* b3 = (const float*)d_in[12];
    const int* src = ei;
    const int* dst = ei + NEDGES;
    float* out = (float*)d_out;

    const int NH_BLKS = (NNODES * HDIM) / 256;
    const int N_BLKS  = (NNODES + 255) / 256;
    const int E_BLKS  = NEDGES / 256;
    const int W_BLKS  = (NNODES * 32 + 255) / 256;

    static bool attr_done = false;
    if (!attr_done) {
        cudaFuncSetAttribute(edge_mlp_v4_kernel,
                             cudaFuncAttributeMaxDynamicSharedMemorySize, SMEM_V4);
        attr_done = true;
    }

    // CSR build (also yields dinv)
    zero_deg_kernel<<<N_BLKS, 256>>>();
    hist_kernel<<<E_BLKS, 256>>>(dst);
    scan_kernel<<<1, 1024>>>();
    fill_kernel<<<E_BLKS, 256>>>(src, dst);

    // encoder
    encoder_kernel<<<NH_BLKS, 256>>>(x, Wn, bn);

    // 3 GCN layers
    for (int l = 0; l < 3; l++) {
        gcn_transform_kernel<<<NNODES / 4, 256>>>(Wc + l * HDIM * HDIM);
        gcn_gather_kernel<<<W_BLKS, 256>>>(bc + l * HDIM);
    }

    pq_kernel<<<NNODES / 4, 256>>>(W1, b1);

    // edge MLP v4: 2500 blocks x 256 thr, 10 tiles/block (5 per half)
    edge_mlp_v4_kernel<<<NEDGES / (TILE_E * 2 * TPH), 256, SMEM_V4>>>(
        src, dst, ea, W1, W2, b2, W3, b3, out);
}

// round 14
// speedup vs baseline: 2.2002x; 1.1216x over previous
#include <cuda_runtime.h>
#include <cstdint>
#include <cstddef>

#define NNODES 50000
#define NEDGES 1600000
#define HDIM   64
#define FNODE  8
#define FEDGE  8
#define NCLS   10

// ---------------- scratch (device globals; no allocation allowed) ----------
__device__ __align__(16) float g_h   [NNODES * HDIM];
__device__ __align__(16) float g_g   [NNODES * HDIM];
__device__ __align__(16) float g_dinv[NNODES];
__device__ __align__(16) float g_P   [NNODES * HDIM];
__device__ __align__(16) float g_Q   [NNODES * HDIM];
__device__ int  g_deg[NNODES];
__device__ int  g_off[NNODES + 1];
__device__ int  g_cur[NNODES];
__device__ int  g_csr[NEDGES];          // src indices grouped by dst

// ---------------- node encoder: h = x @ W_node + b_node --------------------
__global__ void __launch_bounds__(256) encoder_kernel(
    const float* __restrict__ x, const float* __restrict__ Wn,
    const float* __restrict__ bn)
{
    __shared__ float Ws[FNODE * HDIM];
    int tid = threadIdx.x;
    for (int i = tid; i < FNODE * HDIM; i += 256) Ws[i] = Wn[i];
    __syncthreads();
    int t = blockIdx.x * 256 + tid;
    int n = t >> 6, j = t & 63;
    float s = bn[j];
#pragma unroll
    for (int k = 0; k < FNODE; k++)
        s = fmaf(x[n * FNODE + k], Ws[k * HDIM + j], s);
    g_h[t] = s;
}

// ---------------- CSR build ------------------------------------------------
__global__ void zero_deg_kernel() {
    int n = blockIdx.x * 256 + threadIdx.x;
    if (n < NNODES) g_deg[n] = 0;
}
__global__ void hist_kernel(const int* __restrict__ dst) {
    int e = blockIdx.x * 256 + threadIdx.x;
    if (e < NEDGES) atomicAdd(&g_deg[dst[e]], 1);
}
__global__ void __launch_bounds__(1024) scan_kernel() {
    __shared__ int carry;
    __shared__ int warp_tot[32];
    int tid = threadIdx.x, lane = tid & 31, wid = tid >> 5;
    if (tid == 0) carry = 0;
    __syncthreads();
    for (int base = 0; base < NNODES; base += 1024) {
        int n = base + tid;
        int v = (n < NNODES) ? g_deg[n] : 0;
        int x = v;
#pragma unroll
        for (int o = 1; o < 32; o <<= 1) {
            int y = __shfl_up_sync(0xffffffffu, x, o);
            if (lane >= o) x += y;
        }
        if (lane == 31) warp_tot[wid] = x;
        __syncthreads();
        if (wid == 0) {
            int t = warp_tot[lane];
#pragma unroll
            for (int o = 1; o < 32; o <<= 1) {
                int y = __shfl_up_sync(0xffffffffu, t, o);
                if (lane >= o) t += y;
            }
            warp_tot[lane] = t;
        }
        __syncthreads();
        int incl = x + (wid > 0 ? warp_tot[wid - 1] : 0) + carry;
        if (n < NNODES) {
            int excl = incl - v;
            g_off[n] = excl;
            g_cur[n] = excl;
            g_dinv[n] = rsqrtf((float)(v + 1));   // +1 self-loop
        }
        __syncthreads();
        if (tid == 1023) carry = incl;
        __syncthreads();
    }
    if (tid == 0) g_off[NNODES] = NEDGES;
}
__global__ void fill_kernel(const int* __restrict__ src, const int* __restrict__ dst) {
    int e = blockIdx.x * 256 + threadIdx.x;
    if (e < NEDGES) {
        int pos = atomicAdd(&g_cur[dst[e]], 1);
        g_csr[pos] = src[e];
    }
}

// ------------- GCN transform: g = (h @ W) * dinv ---------------------------
__global__ void __launch_bounds__(256) gcn_transform_kernel(
    const float* __restrict__ W)
{
    __shared__ float Ws[HDIM * HDIM];
    __shared__ float hs[4 * HDIM];
    int tid = threadIdx.x;
#pragma unroll 4
    for (int i = tid; i < HDIM * HDIM; i += 256) Ws[i] = W[i];
    int n0 = blockIdx.x * 4;
    hs[tid] = g_h[n0 * HDIM + tid];
    __syncthreads();
    int nn = tid >> 6, j = tid & 63;
    float s = 0.f;
#pragma unroll
    for (int k = 0; k < HDIM; k++)
        s = fmaf(hs[nn * HDIM + k], Ws[k * HDIM + j], s);
    int n = n0 + nn;
    g_g[n * HDIM + j] = s * g_dinv[n];
}

// ------------- GCN gather+finish: warp per node, no atomics ----------------
__global__ void __launch_bounds__(256) gcn_gather_kernel(
    const float* __restrict__ b)
{
    int n = (blockIdx.x * 256 + threadIdx.x) >> 5;
    if (n >= NNODES) return;
    int lane = threadIdx.x & 31;
    int beg = g_off[n], end = g_off[n + 1];
    float a0 = g_g[(size_t)n * HDIM + lane];
    float a1 = g_g[(size_t)n * HDIM + 32 + lane];
    int j = beg;
    for (; j + 4 <= end; j += 4) {
        int s0 = g_csr[j], s1 = g_csr[j + 1], s2 = g_csr[j + 2], s3 = g_csr[j + 3];
        float v00 = g_g[(size_t)s0 * HDIM + lane];
        float v01 = g_g[(size_t)s0 * HDIM + 32 + lane];
        float v10 = g_g[(size_t)s1 * HDIM + lane];
        float v11 = g_g[(size_t)s1 * HDIM + 32 + lane];
        float v20 = g_g[(size_t)s2 * HDIM + lane];
        float v21 = g_g[(size_t)s2 * HDIM + 32 + lane];
        float v30 = g_g[(size_t)s3 * HDIM + lane];
        float v31 = g_g[(size_t)s3 * HDIM + 32 + lane];
        a0 += v00 + v10 + v20 + v30;
        a1 += v01 + v11 + v21 + v31;
    }
    for (; j < end; j++) {
        int s = g_csr[j];
        a0 += g_g[(size_t)s * HDIM + lane];
        a1 += g_g[(size_t)s * HDIM + 32 + lane];
    }
    float di = g_dinv[n];
    g_h[(size_t)n * HDIM + lane]      = fmaxf(fmaf(di, a0, b[lane]),      0.f);
    g_h[(size_t)n * HDIM + 32 + lane] = fmaxf(fmaf(di, a1, b[lane + 32]), 0.f);
}

// ------------- P = h@W1a + b1 ; Q = h@W1b ----------------------------------
__global__ void __launch_bounds__(256) pq_kernel(
    const float* __restrict__ W1, const float* __restrict__ b1)
{
    __shared__ float Ws[2 * HDIM * HDIM];
    __shared__ float hs[4 * HDIM];
    int tid = threadIdx.x;
#pragma unroll 8
    for (int i = tid; i < 2 * HDIM * HDIM; i += 256) Ws[i] = W1[i];
    int n0 = blockIdx.x * 4;
    hs[tid] = g_h[n0 * HDIM + tid];
    __syncthreads();
    int nn = tid >> 6, j = tid & 63;
    float p = b1[j], q = 0.f;
#pragma unroll
    for (int k = 0; k < HDIM; k++) {
        float hv = hs[nn * HDIM + k];
        p = fmaf(hv, Ws[k * HDIM + j], p);
        q = fmaf(hv, Ws[(HDIM + k) * HDIM + j], q);
    }
    int n = n0 + nn;
    g_P[n * HDIM + j] = p;
    g_Q[n * HDIM + j] = q;
}

// ========= edge MLP v5: v4 + conflict-free z1p (row permutation) ===========
// z1p physical row for logical k: phys(k) = (k&3)*16 + (k>>2).
// Phase 1b's 4 scalars from one float4 (logical k = 4c+r, r=0..3) go to
// physical rows {c, c+16, c+32, c+48}; bank = (4c+e)%32, conflict-free.
// Phase 2 reads physical rows 0..63 in order; W2d is staged permuted so
// W2d[phys] corresponds to W2[logical] (only changes fp accumulation order).
#define TILE_E   64
#define TPH      5
#define SP1      68
#define SP2      36
#define OFF_W2D  0
#define OFF_W1C  16384
#define OFF_W3T  18432
#define OFF_B2   19712
#define OFF_B3   19840
#define OFF_HALF 19968
#define HALF_SZ  26624
#define SMEM_V4  (OFF_HALF + 2 * HALF_SZ)   // 73216

__global__ void __launch_bounds__(256, 3) edge_mlp_v5_kernel(
    const int*   __restrict__ src, const int* __restrict__ dst,
    const float* __restrict__ ea,
    const float* __restrict__ W1,
    const float* __restrict__ W2,  const float* __restrict__ b2,
    const float* __restrict__ W3,  const float* __restrict__ b3,
    float*       __restrict__ out)
{
    extern __shared__ __align__(16) char sm[];
    float2* W2d  = (float2*)(sm + OFF_W2D);
    float*  W1cs = (float*)(sm + OFF_W1C);
    float*  W3ts = (float*)(sm + OFF_W3T);
    float*  b2s  = (float*)(sm + OFF_B2);
    float*  b3s  = (float*)(sm + OFF_B3);

    int tid = threadIdx.x;
    int h   = tid >> 7;
    int t128 = tid & 127;

    float* z1p = (float*)(sm + OFF_HALF + h * HALF_SZ);
    float* z2s = z1p + HDIM * SP1;

    // ---- stage weights once; W2d permuted: W2d[phys] = W2[logical] ----
    for (int i = tid; i < HDIM * 32; i += 256) {
        int kp = i >> 5, j = i & 31;
        int kl = (kp & 15) * 4 + (kp >> 4);      // inverse of phys(k)
        float w = W2[kl * 32 + j];
        W2d[i] = make_float2(w, w);
    }
    for (int i = tid; i < FEDGE * HDIM; i += 256) W1cs[i] = W1[2 * HDIM * HDIM + i];
    for (int i = tid; i < NCLS * 32; i += 256) {
        int j = i >> 5, k = i & 31;
        W3ts[i] = W3[k * NCLS + j];
    }
    if (tid < 32)   b2s[tid] = b2[tid];
    if (tid < NCLS) b3s[tid] = b3[tid];
    __syncthreads();

    uint32_t z1b = (uint32_t)__cvta_generic_to_shared(z1p);
    uint32_t w2b = (uint32_t)__cvta_generic_to_shared(W2d);

    // phase-1a mapping: warp = 32 consecutive edges (conflict-free STS)
    int el1 = t128 & 63;
    int hf1 = t128 >> 6;
    // phase-3 mapping (unchanged)
    int el3 = t128 >> 1;
    int hf3 = t128 & 1;
    // phase-2 mapping
    int eg = t128 & 15;
    int cg = (t128 >> 4) & 7;
    int j0 = cg * 4;
    int lane = t128 & 31, wrp = t128 >> 5;
    int bar = h + 1;

#pragma unroll 1
    for (int it = 0; it < TPH; ++it) {
        int ebase = (blockIdx.x * (2 * TPH) + h * TPH + it) * TILE_E;

        // -------- Phase 1a: z1p[phys(k)][e] = attr @ W1c (raw) -------------
        {
            int e = ebase + el1;
            const float4* eap = (const float4*)(ea + (size_t)e * FEDGE);
            float4 a0 = eap[0], a1 = eap[1];
            float av[8] = {a0.x, a0.y, a0.z, a0.w, a1.x, a1.y, a1.z, a1.w};
            const float4* W1c4 = (const float4*)W1cs;
            float4 acc[8];
#pragma unroll
            for (int q = 0; q < 8; q++) acc[q] = make_float4(0.f, 0.f, 0.f, 0.f);
#pragma unroll
            for (int k = 0; k < FEDGE; k++) {
                float ak = av[k];
#pragma unroll
                for (int q = 0; q < 8; q++) {
                    float4 w = W1c4[k * 16 + hf1 * 8 + q];
                    acc[q].x = fmaf(ak, w.x, acc[q].x);
                    acc[q].y = fmaf(ak, w.y, acc[q].y);
                    acc[q].z = fmaf(ak, w.z, acc[q].z);
                    acc[q].w = fmaf(ak, w.w, acc[q].w);
                }
            }
#pragma unroll
            for (int q = 0; q < 8; q++) {
                int c = hf1 * 8 + q;                 // logical k = 4c + r
                float* zp = &z1p[c * SP1 + el1];     // phys rows c + 16r
                zp[0]             = acc[q].x;
                zp[16 * SP1]      = acc[q].y;
                zp[32 * SP1]      = acc[q].z;
                zp[48 * SP1]      = acc[q].w;
            }
        }
        asm volatile("bar.sync %0, 128;" :: "r"(bar) : "memory");

        // -------- Phase 1b: z1p += P[s]+Q[d]; relu (coalesced, CF banks) ---
        {
#pragma unroll
            for (int i = 0; i < 8; i++) {
                int e = wrp * 4 + (lane >> 3) + (i >> 1) * 16;   // 0..63
                int c = (lane & 7) + (i & 1) * 8;                // chunk 0..15
                int ge = ebase + e;
                int s = src[ge], d = dst[ge];
                float4 p = *(const float4*)(g_P + (size_t)s * HDIM + c * 4);
                float4 q = *(const float4*)(g_Q + (size_t)d * HDIM + c * 4);
                float* zp = &z1p[c * SP1 + e];       // phys rows c + 16r
                zp[0]        = fmaxf(zp[0]        + p.x + q.x, 0.f);
                zp[16 * SP1] = fmaxf(zp[16 * SP1] + p.y + q.y, 0.f);
                zp[32 * SP1] = fmaxf(zp[32 * SP1] + p.z + q.z, 0.f);
                zp[48 * SP1] = fmaxf(zp[48 * SP1] + p.w + q.w, 0.f);
            }
        }
        asm volatile("bar.sync %0, 128;" :: "r"(bar) : "memory");

        // ---------------- Phase 2 (reads physical rows; W2d pre-permuted) --
        {
            uint64_t acc01[4], acc23[4];
#pragma unroll
            for (int j = 0; j < 4; j++) {
                float bv = b2s[j0 + j];
                uint64_t bb;
                asm("mov.b64 %0, {%1, %1};" : "=l"(bb) : "f"(bv));
                acc01[j] = bb; acc23[j] = bb;
            }
            uint32_t za = z1b + eg * 16;
            uint32_t wa = w2b + j0 * 8;
#pragma unroll 16
            for (int k = 0; k < HDIM; k++) {
                uint64_t z01, z23, w0, w1, w2v, w3v;
                asm("ld.shared.v2.b64 {%0,%1}, [%2];"
                    : "=l"(z01), "=l"(z23) : "r"(za + k * (SP1 * 4)));
                asm("ld.shared.v2.b64 {%0,%1}, [%2];"
                    : "=l"(w0), "=l"(w1) : "r"(wa + k * 256));
                asm("ld.shared.v2.b64 {%0,%1}, [%2];"
                    : "=l"(w2v), "=l"(w3v) : "r"(wa + k * 256 + 16));
                asm("fma.rn.f32x2 %0, %1, %2, %0;" : "+l"(acc01[0]) : "l"(z01), "l"(w0));
                asm("fma.rn.f32x2 %0, %1, %2, %0;" : "+l"(acc23[0]) : "l"(z23), "l"(w0));
                asm("fma.rn.f32x2 %0, %1, %2, %0;" : "+l"(acc01[1]) : "l"(z01), "l"(w1));
                asm("fma.rn.f32x2 %0, %1, %2, %0;" : "+l"(acc23[1]) : "l"(z23), "l"(w1));
                asm("fma.rn.f32x2 %0, %1, %2, %0;" : "+l"(acc01[2]) : "l"(z01), "l"(w2v));
                asm("fma.rn.f32x2 %0, %1, %2, %0;" : "+l"(acc23[2]) : "l"(z23), "l"(w2v));
                asm("fma.rn.f32x2 %0, %1, %2, %0;" : "+l"(acc01[3]) : "l"(z01), "l"(w3v));
                asm("fma.rn.f32x2 %0, %1, %2, %0;" : "+l"(acc23[3]) : "l"(z23), "l"(w3v));
            }
            float v0[4], v1[4], v2[4], v3[4];
#pragma unroll
            for (int j = 0; j < 4; j++) {
                float lo, hi;
                asm("mov.b64 {%0,%1}, %2;" : "=f"(lo), "=f"(hi) : "l"(acc01[j]));
                v0[j] = fmaxf(lo, 0.f); v1[j] = fmaxf(hi, 0.f);
                asm("mov.b64 {%0,%1}, %2;" : "=f"(lo), "=f"(hi) : "l"(acc23[j]));
                v2[j] = fmaxf(lo, 0.f); v3[j] = fmaxf(hi, 0.f);
            }
            int e0 = eg * 4;
            *(float4*)&z2s[(e0 + 0) * SP2 + j0] = make_float4(v0[0], v0[1], v0[2], v0[3]);
            *(float4*)&z2s[(e0 + 1) * SP2 + j0] = make_float4(v1[0], v1[1], v1[2], v1[3]);
            *(float4*)&z2s[(e0 + 2) * SP2 + j0] = make_float4(v2[0], v2[1], v2[2], v2[3]);
            *(float4*)&z2s[(e0 + 3) * SP2 + j0] = make_float4(v3[0], v3[1], v3[2], v3[3]);
        }
        asm volatile("bar.sync %0, 128;" :: "r"(bar) : "memory");

        // ---------------- Phase 3 ----------------
        {
            int jo = hf3 * 5;
            float acc[5];
#pragma unroll
            for (int j = 0; j < 5; j++) acc[j] = b3s[jo + j];
            const float4* z2v = (const float4*)&z2s[el3 * SP2];
#pragma unroll
            for (int k4 = 0; k4 < 8; k4++) {
                float4 z = z2v[k4];
#pragma unroll
                for (int j = 0; j < 5; j++) {
                    float4 w = *(const float4*)&W3ts[(jo + j) * 32 + k4 * 4];
                    acc[j] = fmaf(z.x, w.x, acc[j]);
                    acc[j] = fmaf(z.y, w.y, acc[j]);
                    acc[j] = fmaf(z.z, w.z, acc[j]);
                    acc[j] = fmaf(z.w, w.w, acc[j]);
                }
            }
            float* op = out + (size_t)(ebase + el3) * NCLS + jo;
#pragma unroll
            for (int j = 0; j < 5; j++) op[j] = acc[j];
        }
        asm volatile("bar.sync %0, 128;" :: "r"(bar) : "memory");
    }
}

// ---------------------------------------------------------------------------
extern "C" void kernel_launch(void* const* d_in, const int* in_sizes, int n_in,
                              void* d_out, int out_size)
{
    const float* x  = (const float*)d_in[0];
    const int*   ei = (const int*)  d_in[1];
    const float* ea = (const float*)d_in[2];
    const float* Wn = (const float*)d_in[3];
    const float* bn = (const float*)d_in[4];
    const float* Wc = (const float*)d_in[5];
    const float* bc = (const float*)d_in[6];
    const float* W1 = (const float*)d_in[7];
    const float* b1 = (const float*)d_in[8];
    const float* W2 = (const float*)d_in[9];
    const float* b2 = (const float*)d_in[10];
    const float* W3 = (const float*)d_in[11];
    const float* b3 = (const float*)d_in[12];
    const int* src = ei;
    const int* dst = ei + NEDGES;
    float* out = (float*)d_out;

    const int NH_BLKS = (NNODES * HDIM) / 256;
    const int N_BLKS  = (NNODES + 255) / 256;
    const int E_BLKS  = NEDGES / 256;
    const int W_BLKS  = (NNODES * 32 + 255) / 256;

    static bool attr_done = false;
    if (!attr_done) {
        cudaFuncSetAttribute(edge_mlp_v5_kernel,
                             cudaFuncAttributeMaxDynamicSharedMemorySize, SMEM_V4);
        attr_done = true;
    }

    // CSR build (also yields dinv)
    zero_deg_kernel<<<N_BLKS, 256>>>();
    hist_kernel<<<E_BLKS, 256>>>(dst);
    scan_kernel<<<1, 1024>>>();
    fill_kernel<<<E_BLKS, 256>>>(src, dst);

    // encoder
    encoder_kernel<<<NH_BLKS, 256>>>(x, Wn, bn);

    // 3 GCN layers
    for (int l = 0; l < 3; l++) {
        gcn_transform_kernel<<<NNODES / 4, 256>>>(Wc + l * HDIM * HDIM);
        gcn_gather_kernel<<<W_BLKS, 256>>>(bc + l * HDIM);
    }

    pq_kernel<<<NNODES / 4, 256>>>(W1, b1);

    edge_mlp_v5_kernel<<<NEDGES / (TILE_E * 2 * TPH), 256, SMEM_V4>>>(
        src, dst, ea, W1, W2, b2, W3, b3, out);
}

// round 16
// speedup vs baseline: 2.2740x; 1.0335x over previous
#include <cuda_runtime.h>
#include <cstdint>
#include <cstddef>

#define NNODES 50000
#define NEDGES 1600000
#define HDIM   64
#define FNODE  8
#define FEDGE  8
#define NCLS   10

// ---------------- scratch (device globals; no allocation allowed) ----------
__device__ __align__(16) float g_h   [NNODES * HDIM];
__device__ __align__(16) float g_g   [NNODES * HDIM];
__device__ __align__(16) float g_dinv[NNODES];
__device__ __align__(16) float g_P   [NNODES * HDIM];
__device__ __align__(16) float g_Q   [NNODES * HDIM];
__device__ int  g_deg[NNODES];
__device__ int  g_off[NNODES + 1];
__device__ int  g_cur[NNODES];
__device__ int  g_csr[NEDGES];          // src indices grouped by dst

// ---------------- node encoder: h = x @ W_node + b_node --------------------
__global__ void __launch_bounds__(256) encoder_kernel(
    const float* __restrict__ x, const float* __restrict__ Wn,
    const float* __restrict__ bn)
{
    __shared__ float Ws[FNODE * HDIM];
    int tid = threadIdx.x;
    for (int i = tid; i < FNODE * HDIM; i += 256) Ws[i] = Wn[i];
    __syncthreads();
    int t = blockIdx.x * 256 + tid;
    int n = t >> 6, j = t & 63;
    float s = bn[j];
#pragma unroll
    for (int k = 0; k < FNODE; k++)
        s = fmaf(x[n * FNODE + k], Ws[k * HDIM + j], s);
    g_h[t] = s;
}

// ---------------- CSR build ------------------------------------------------
__global__ void zero_deg_kernel() {
    int n = blockIdx.x * 256 + threadIdx.x;
    if (n < NNODES) g_deg[n] = 0;
}
__global__ void hist_kernel(const int* __restrict__ dst) {
    int e = blockIdx.x * 256 + threadIdx.x;
    if (e < NEDGES) atomicAdd(&g_deg[dst[e]], 1);
}
__global__ void __launch_bounds__(1024) scan_kernel() {
    __shared__ int carry;
    __shared__ int warp_tot[32];
    int tid = threadIdx.x, lane = tid & 31, wid = tid >> 5;
    if (tid == 0) carry = 0;
    __syncthreads();
    for (int base = 0; base < NNODES; base += 1024) {
        int n = base + tid;
        int v = (n < NNODES) ? g_deg[n] : 0;
        int x = v;
#pragma unroll
        for (int o = 1; o < 32; o <<= 1) {
            int y = __shfl_up_sync(0xffffffffu, x, o);
            if (lane >= o) x += y;
        }
        if (lane == 31) warp_tot[wid] = x;
        __syncthreads();
        if (wid == 0) {
            int t = warp_tot[lane];
#pragma unroll
            for (int o = 1; o < 32; o <<= 1) {
                int y = __shfl_up_sync(0xffffffffu, t, o);
                if (lane >= o) t += y;
            }
            warp_tot[lane] = t;
        }
        __syncthreads();
        int incl = x + (wid > 0 ? warp_tot[wid - 1] : 0) + carry;
        if (n < NNODES) {
            int excl = incl - v;
            g_off[n] = excl;
            g_cur[n] = excl;
            g_dinv[n] = rsqrtf((float)(v + 1));   // +1 self-loop
        }
        __syncthreads();
        if (tid == 1023) carry = incl;
        __syncthreads();
    }
    if (tid == 0) g_off[NNODES] = NEDGES;
}
__global__ void fill_kernel(const int* __restrict__ src, const int* __restrict__ dst) {
    int e = blockIdx.x * 256 + threadIdx.x;
    if (e < NEDGES) {
        int pos = atomicAdd(&g_cur[dst[e]], 1);
        g_csr[pos] = src[e];
    }
}

// ------------- GCN transform: g = (h @ W) * dinv ---------------------------
__global__ void __launch_bounds__(256) gcn_transform_kernel(
    const float* __restrict__ W)
{
    __shared__ float Ws[HDIM * HDIM];
    __shared__ float hs[4 * HDIM];
    int tid = threadIdx.x;
#pragma unroll 4
    for (int i = tid; i < HDIM * HDIM; i += 256) Ws[i] = W[i];
    int n0 = blockIdx.x * 4;
    hs[tid] = g_h[n0 * HDIM + tid];
    __syncthreads();
    int nn = tid >> 6, j = tid & 63;
    float s = 0.f;
#pragma unroll
    for (int k = 0; k < HDIM; k++)
        s = fmaf(hs[nn * HDIM + k], Ws[k * HDIM + j], s);
    int n = n0 + nn;
    g_g[n * HDIM + j] = s * g_dinv[n];
}

// ------------- GCN gather+finish: warp per node, no atomics ----------------
__global__ void __launch_bounds__(256) gcn_gather_kernel(
    const float* __restrict__ b)
{
    int n = (blockIdx.x * 256 + threadIdx.x) >> 5;
    if (n >= NNODES) return;
    int lane = threadIdx.x & 31;
    int beg = g_off[n], end = g_off[n + 1];
    float a0 = g_g[(size_t)n * HDIM + lane];
    float a1 = g_g[(size_t)n * HDIM + 32 + lane];
    int j = beg;
    for (; j + 4 <= end; j += 4) {
        int s0 = g_csr[j], s1 = g_csr[j + 1], s2 = g_csr[j + 2], s3 = g_csr[j + 3];
        float v00 = g_g[(size_t)s0 * HDIM + lane];
        float v01 = g_g[(size_t)s0 * HDIM + 32 + lane];
        float v10 = g_g[(size_t)s1 * HDIM + lane];
        float v11 = g_g[(size_t)s1 * HDIM + 32 + lane];
        float v20 = g_g[(size_t)s2 * HDIM + lane];
        float v21 = g_g[(size_t)s2 * HDIM + 32 + lane];
        float v30 = g_g[(size_t)s3 * HDIM + lane];
        float v31 = g_g[(size_t)s3 * HDIM + 32 + lane];
        a0 += v00 + v10 + v20 + v30;
        a1 += v01 + v11 + v21 + v31;
    }
    for (; j < end; j++) {
        int s = g_csr[j];
        a0 += g_g[(size_t)s * HDIM + lane];
        a1 += g_g[(size_t)s * HDIM + 32 + lane];
    }
    float di = g_dinv[n];
    g_h[(size_t)n * HDIM + lane]      = fmaxf(fmaf(di, a0, b[lane]),      0.f);
    g_h[(size_t)n * HDIM + 32 + lane] = fmaxf(fmaf(di, a1, b[lane + 32]), 0.f);
}

// ------------- P = h@W1a + b1 ; Q = h@W1b ----------------------------------
__global__ void __launch_bounds__(256) pq_kernel(
    const float* __restrict__ W1, const float* __restrict__ b1)
{
    __shared__ float Ws[2 * HDIM * HDIM];
    __shared__ float hs[4 * HDIM];
    int tid = threadIdx.x;
#pragma unroll 8
    for (int i = tid; i < 2 * HDIM * HDIM; i += 256) Ws[i] = W1[i];
    int n0 = blockIdx.x * 4;
    hs[tid] = g_h[n0 * HDIM + tid];
    __syncthreads();
    int nn = tid >> 6, j = tid & 63;
    float p = b1[j], q = 0.f;
#pragma unroll
    for (int k = 0; k < HDIM; k++) {
        float hv = hs[nn * HDIM + k];
        p = fmaf(hv, Ws[k * HDIM + j], p);
        q = fmaf(hv, Ws[(HDIM + k) * HDIM + j], q);
    }
    int n = n0 + nn;
    g_P[n * HDIM + j] = p;
    g_Q[n * HDIM + j] = q;
}

// ===== edge MLP v6: fused phase1 + warp-local phase2 (no z redundancy) =====
#define TILE_E   64
#define TPH      5
#define SP1      68
#define SP2      36
#define OFF_W2D  0
#define OFF_W1C  16384
#define OFF_W3T  18432
#define OFF_B2   19712
#define OFF_B3   19840
#define OFF_HALF 19968
#define HALF_SZ  26624
#define SMEM_V4  (OFF_HALF + 2 * HALF_SZ)   // 73216

__global__ void __launch_bounds__(256, 3) edge_mlp_v6_kernel(
    const int*   __restrict__ src, const int* __restrict__ dst,
    const float* __restrict__ ea,
    const float* __restrict__ W1,
    const float* __restrict__ W2,  const float* __restrict__ b2,
    const float* __restrict__ W3,  const float* __restrict__ b3,
    float*       __restrict__ out)
{
    extern __shared__ __align__(16) char sm[];
    float2* W2d  = (float2*)(sm + OFF_W2D);
    float*  W1cs = (float*)(sm + OFF_W1C);
    float*  W3ts = (float*)(sm + OFF_W3T);
    float*  b2s  = (float*)(sm + OFF_B2);
    float*  b3s  = (float*)(sm + OFF_B3);

    int tid = threadIdx.x;
    int h   = tid >> 7;
    int t128 = tid & 127;

    float* z1p = (float*)(sm + OFF_HALF + h * HALF_SZ);
    float* z2s = z1p + HDIM * SP1;

    // ---- stage weights once; W2d permuted: W2d[phys] = W2[logical] ----
    for (int i = tid; i < HDIM * 32; i += 256) {
        int kp = i >> 5, j = i & 31;
        int kl = (kp & 15) * 4 + (kp >> 4);      // inverse of phys(k)
        float w = W2[kl * 32 + j];
        W2d[i] = make_float2(w, w);
    }
    for (int i = tid; i < FEDGE * HDIM; i += 256) W1cs[i] = W1[2 * HDIM * HDIM + i];
    for (int i = tid; i < NCLS * 32; i += 256) {
        int j = i >> 5, k = i & 31;
        W3ts[i] = W3[k * NCLS + j];
    }
    if (tid < 32)   b2s[tid] = b2[tid];
    if (tid < NCLS) b3s[tid] = b3[tid];
    __syncthreads();

    uint32_t z1b = (uint32_t)__cvta_generic_to_shared(z1p);
    uint32_t w2b = (uint32_t)__cvta_generic_to_shared(W2d);

    int lane = t128 & 31, wrp = t128 >> 5;
    int sub = lane & 3;
    int jc  = lane >> 2;
    int j0  = jc * 4;
    int e2base = wrp * 16 + sub * 4;
    int el3 = t128 >> 1;
    int hf3 = t128 & 1;
    int bar = h + 1;

#pragma unroll 1
    for (int it = 0; it < TPH; ++it) {
        int ebase = (blockIdx.x * (2 * TPH) + h * TPH + it) * TILE_E;

        // -------- Phase 1 (fused): z1p = relu(P[s]+Q[d]+attr@W1c) ----------
        {
            const float4* W1c4 = (const float4*)W1cs;
#pragma unroll
            for (int ep = 0; ep < 4; ep++) {
                int e  = wrp * 4 + (lane >> 3) + ep * 16;     // 0..63
                int ge = ebase + e;
                int s = src[ge], d = dst[ge];
                const float4* eap = (const float4*)(ea + (size_t)ge * FEDGE);
                float4 a0 = eap[0], a1 = eap[1];
                float av[8] = {a0.x, a0.y, a0.z, a0.w, a1.x, a1.y, a1.z, a1.w};
#pragma unroll
                for (int hc = 0; hc < 2; hc++) {
                    int c = (lane & 7) + hc * 8;              // chunk 0..15
                    float4 p = *(const float4*)(g_P + (size_t)s * HDIM + c * 4);
                    float4 q = *(const float4*)(g_Q + (size_t)d * HDIM + c * 4);
                    float4 acc;
                    acc.x = p.x + q.x; acc.y = p.y + q.y;
                    acc.z = p.z + q.z; acc.w = p.w + q.w;
#pragma unroll
                    for (int k8 = 0; k8 < 8; k8++) {
                        float4 wv = W1c4[k8 * 16 + c];
                        acc.x = fmaf(av[k8], wv.x, acc.x);
                        acc.y = fmaf(av[k8], wv.y, acc.y);
                        acc.z = fmaf(av[k8], wv.z, acc.z);
                        acc.w = fmaf(av[k8], wv.w, acc.w);
                    }
                    float* zp = &z1p[c * SP1 + e];            // phys rows c+16r
                    zp[0]        = fmaxf(acc.x, 0.f);
                    zp[16 * SP1] = fmaxf(acc.y, 0.f);
                    zp[32 * SP1] = fmaxf(acc.z, 0.f);
                    zp[48 * SP1] = fmaxf(acc.w, 0.f);
                }
            }
        }
        asm volatile("bar.sync %0, 128;" :: "r"(bar) : "memory");

        // ---------------- Phase 2: warp-local edges, packed f32x2 ----------
        {
            uint64_t acc01[4], acc23[4];
#pragma unroll
            for (int j = 0; j < 4; j++) {
                float bv = b2s[j0 + j];
                uint64_t bb;
                asm("mov.b64 %0, {%1, %1};" : "=l"(bb) : "f"(bv));
                acc01[j] = bb; acc23[j] = bb;
            }
            uint32_t za = z1b + e2base * 4;      // 4 edges = 16B
            uint32_t wa = w2b + j0 * 8;
#pragma unroll 16
            for (int k = 0; k < HDIM; k++) {
                uint64_t z01, z23, w0, w1, w2v, w3v;
                asm("ld.shared.v2.b64 {%0,%1}, [%2];"
                    : "=l"(z01), "=l"(z23) : "r"(za + k * (SP1 * 4)));
                asm("ld.shared.v2.b64 {%0,%1}, [%2];"
                    : "=l"(w0), "=l"(w1) : "r"(wa + k * 256));
                asm("ld.shared.v2.b64 {%0,%1}, [%2];"
                    : "=l"(w2v), "=l"(w3v) : "r"(wa + k * 256 + 16));
                asm("fma.rn.f32x2 %0, %1, %2, %0;" : "+l"(acc01[0]) : "l"(z01), "l"(w0));
                asm("fma.rn.f32x2 %0, %1, %2, %0;" : "+l"(acc23[0]) : "l"(z23), "l"(w0));
                asm("fma.rn.f32x2 %0, %1, %2, %0;" : "+l"(acc01[1]) : "l"(z01), "l"(w1));
                asm("fma.rn.f32x2 %0, %1, %2, %0;" : "+l"(acc23[1]) : "l"(z23), "l"(w1));
                asm("fma.rn.f32x2 %0, %1, %2, %0;" : "+l"(acc01[2]) : "l"(z01), "l"(w2v));
                asm("fma.rn.f32x2 %0, %1, %2, %0;" : "+l"(acc23[2]) : "l"(z23), "l"(w2v));
                asm("fma.rn.f32x2 %0, %1, %2, %0;" : "+l"(acc01[3]) : "l"(z01), "l"(w3v));
                asm("fma.rn.f32x2 %0, %1, %2, %0;" : "+l"(acc23[3]) : "l"(z23), "l"(w3v));
            }
            float v0[4], v1[4], v2[4], v3[4];
#pragma unroll
            for (int j = 0; j < 4; j++) {
                float lo, hi;
                asm("mov.b64 {%0,%1}, %2;" : "=f"(lo), "=f"(hi) : "l"(acc01[j]));
                v0[j] = fmaxf(lo, 0.f); v1[j] = fmaxf(hi, 0.f);
                asm("mov.b64 {%0,%1}, %2;" : "=f"(lo), "=f"(hi) : "l"(acc23[j]));
                v2[j] = fmaxf(lo, 0.f); v3[j] = fmaxf(hi, 0.f);
            }
            *(float4*)&z2s[(e2base + 0) * SP2 + j0] = make_float4(v0[0], v0[1], v0[2], v0[3]);
            *(float4*)&z2s[(e2base + 1) * SP2 + j0] = make_float4(v1[0], v1[1], v1[2], v1[3]);
            *(float4*)&z2s[(e2base + 2) * SP2 + j0] = make_float4(v2[0], v2[1], v2[2], v2[3]);
            *(float4*)&z2s[(e2base + 3) * SP2 + j0] = make_float4(v3[0], v3[1], v3[2], v3[3]);
        }
        asm volatile("bar.sync %0, 128;" :: "r"(bar) : "memory");

        // ---------------- Phase 3 ----------------
        {
            int jo = hf3 * 5;
            float acc[5];
#pragma unroll
            for (int j = 0; j < 5; j++) acc[j] = b3s[jo + j];
            const float4* z2v = (const float4*)&z2s[el3 * SP2];
#pragma unroll
            for (int k4 = 0; k4 < 8; k4++) {
                float4 z = z2v[k4];
#pragma unroll
                for (int j = 0; j < 5; j++) {
                    float4 w = *(const float4*)&W3ts[(jo + j) * 32 + k4 * 4];
                    acc[j] = fmaf(z.x, w.x, acc[j]);
                    acc[j] = fmaf(z.y, w.y, acc[j]);
                    acc[j] = fmaf(z.z, w.z, acc[j]);
                    acc[j] = fmaf(z.w, w.w, acc[j]);
                }
            }
            float* op = out + (size_t)(ebase + el3) * NCLS + jo;
#pragma unroll
            for (int j = 0; j < 5; j++) op[j] = acc[j];
        }
        asm volatile("bar.sync %0, 128;" :: "r"(bar) : "memory");
    }
}

// ---------------------------------------------------------------------------
extern "C" void kernel_launch(void* const* d_in, const int* in_sizes, int n_in,
                              void* d_out, int out_size)
{
    const float* x  = (const float*)d_in[0];
    const int*   ei = (const int*)  d_in[1];
    const float* ea = (const float*)d_in[2];
    const float* Wn = (const float*)d_in[3];
    const float* bn = (const float*)d_in[4];
    const float* Wc = (const float*)d_in[5];
    const float* bc = (const float*)d_in[6];
    const float* W1 = (const float*)d_in[7];
    const float* b1 = (const float*)d_in[8];
    const float* W2 = (const float*)d_in[9];
    const float* b2 = (const float*)d_in[10];
    const float* W3 = (const float*)d_in[11];
    const float* b3 = (const float*)d_in[12];
    const int* src = ei;
    const int* dst = ei + NEDGES;
    float* out = (float*)d_out;

    const int NH_BLKS = (NNODES * HDIM) / 256;
    const int N_BLKS  = (NNODES + 255) / 256;
    const int E_BLKS  = NEDGES / 256;
    const int W_BLKS  = (NNODES * 32 + 255) / 256;

    static bool attr_done = false;
    if (!attr_done) {
        cudaFuncSetAttribute(edge_mlp_v6_kernel,
                             cudaFuncAttributeMaxDynamicSharedMemorySize, SMEM_V4);
        attr_done = true;
    }

    // CSR build (also yields dinv)
    zero_deg_kernel<<<N_BLKS, 256>>>();
    hist_kernel<<<E_BLKS, 256>>>(dst);
    scan_kernel<<<1, 1024>>>();
    fill_kernel<<<E_BLKS, 256>>>(src, dst);

    // encoder
    encoder_kernel<<<NH_BLKS, 256>>>(x, Wn, bn);

    // 3 GCN layers
    for (int l = 0; l < 3; l++) {
        gcn_transform_kernel<<<NNODES / 4, 256>>>(Wc + l * HDIM * HDIM);
        gcn_gather_kernel<<<W_BLKS, 256>>>(bc + l * HDIM);
    }

    pq_kernel<<<NNODES / 4, 256>>>(W1, b1);

    edge_mlp_v6_kernel<<<NEDGES / (TILE_E * 2 * TPH), 256, SMEM_V4>>>(
        src, dst, ea, W1, W2, b2, W3, b3, out);
}